// round 13
// baseline (speedup 1.0000x reference)
#include <cuda_runtime.h>
#include <cuda_bf16.h>
#include <math.h>
#include <stdint.h>

#define Bx    256
#define OBSx  256
#define DINx  512
#define Dx    1024
#define Mx    32
#define HIDx  16
#define NSYx  64
#define ITERSx 4
#define SYNCHx 2080
#define BDx   (Bx * Dx)          // 262144
#define BDMx  (Bx * Dx * Mx)     // 8388608

// ---------------- scratch (static device globals) ----------------
__device__ float g_y[4 * Bx * 2 * Dx];               // split-K partial slices
__device__ __align__(16) __nv_bfloat16 g_w1bh[Dx * 1024];  // [d][h*32+m] bf16 hi
__device__ __align__(16) __nv_bfloat16 g_w1bl[Dx * 1024];  // [d][h*32+m] bf16 lo
__device__ float g_w2t[Dx * 32];
__device__ float g_decay[Mx * SYNCHx];
__device__ float g_invden[SYNCHx];
__device__ int   g_tri_i[SYNCHx];
__device__ int   g_tri_j[SYNCHx];
__device__ int   g_dones[Bx];
__device__ __align__(16) float g_hst[ITERSx][BDx];   // [i][b*1024+d]
__device__ __align__(16) float g_hat[ITERSx][BDx];   // [i][d*256+b]

__device__ __align__(256) __nv_bfloat16 g_obshi[Bx * OBSx];
__device__ __align__(256) __nv_bfloat16 g_obslo[Bx * OBSx];
__device__ __align__(256) __nv_bfloat16 g_prehi[Bx * (DINx + Dx)];
__device__ __align__(256) __nv_bfloat16 g_prelo[Bx * (DINx + Dx)];
__device__ __align__(256) __nv_bfloat16 g_h1hi[Bx * Dx];
__device__ __align__(256) __nv_bfloat16 g_h1lo[Bx * Dx];
__device__ __align__(256) __nv_bfloat16 g_wb1hi[1024 * 256];
__device__ __align__(256) __nv_bfloat16 g_wb1lo[1024 * 256];
__device__ __align__(256) __nv_bfloat16 g_wb2hi[1024 * 512];
__device__ __align__(256) __nv_bfloat16 g_wb2lo[1024 * 512];
__device__ __align__(256) __nv_bfloat16 g_ws1hi[2048 * 1536];
__device__ __align__(256) __nv_bfloat16 g_ws1lo[2048 * 1536];
__device__ __align__(256) __nv_bfloat16 g_ws2hi[2048 * 1024];
__device__ __align__(256) __nv_bfloat16 g_ws2lo[2048 * 1024];

__device__ __forceinline__ float sigf(float x) {
    return __fdividef(1.0f, 1.0f + __expf(-x));
}
__device__ __forceinline__ void split2(float v, __nv_bfloat16* h, __nv_bfloat16* l) {
    __nv_bfloat16 hh = __float2bfloat16(v);
    *h = hh;
    *l = __float2bfloat16(v - __bfloat162float(hh));
}
__device__ __forceinline__ void split_pack(float v0, float v1, uint32_t& ph, uint32_t& pl) {
    __nv_bfloat16 h0 = __float2bfloat16(v0);
    __nv_bfloat16 h1 = __float2bfloat16(v1);
    __nv_bfloat16 l0 = __float2bfloat16(v0 - __bfloat162float(h0));
    __nv_bfloat16 l1 = __float2bfloat16(v1 - __bfloat162float(h1));
    unsigned short u0, u1;
    memcpy(&u0, &h0, 2); memcpy(&u1, &h1, 2);
    ph = (uint32_t)u0 | ((uint32_t)u1 << 16);
    memcpy(&u0, &l0, 2); memcpy(&u1, &l1, 2);
    pl = (uint32_t)u0 | ((uint32_t)u1 << 16);
}

// ================= PTX helpers =================
__device__ __forceinline__ uint32_t smem_u32(const void* p) {
    uint32_t a;
    asm("{ .reg .u64 t; cvta.to.shared.u64 t, %1; cvt.u32.u64 %0, t; }" : "=r"(a) : "l"(p));
    return a;
}
#define SW128(off) ((off) ^ (((off) >> 3) & 0x70))
#define SW64(off)  ((off) ^ (((off) >> 3) & 0x30))
#define CP_ASYNC16(dst, src) \
    asm volatile("cp.async.cg.shared.global [%0], [%1], 16;" :: "r"(dst), "l"(src))
#define CP_COMMIT()  asm volatile("cp.async.commit_group;" ::: "memory")
#define CP_WAIT(n)   asm volatile("cp.async.wait_group %0;" :: "n"(n) : "memory")
#define LDSM4(r, addr) \
    asm volatile("ldmatrix.sync.aligned.m8n8.x4.shared.b16 {%0,%1,%2,%3}, [%4];" \
        : "=r"((r)[0]), "=r"((r)[1]), "=r"((r)[2]), "=r"((r)[3]) : "r"(addr))
#define MMA16816(acc, a, b0, b1) \
    asm volatile("mma.sync.aligned.m16n8k16.row.col.f32.bf16.bf16.f32 " \
        "{%0,%1,%2,%3}, {%4,%5,%6,%7}, {%8,%9}, {%0,%1,%2,%3};" \
        : "+f"((acc)[0]), "+f"((acc)[1]), "+f"((acc)[2]), "+f"((acc)[3]) \
        : "r"((a)[0]), "r"((a)[1]), "r"((a)[2]), "r"((a)[3]), "r"(b0), "r"(b1))

// ================= split-bf16 HMMA GEMM, split-K with K-base offset =========
#define GBUF_BYTES 32768
#define GSTAGES 3
__global__ void __launch_bounds__(256) k_tgemm(
    const __nv_bfloat16* __restrict__ Ahi, const __nv_bfloat16* __restrict__ Alo,
    const __nv_bfloat16* __restrict__ Bhi, const __nv_bfloat16* __restrict__ Blo,
    float* __restrict__ C, int kbase, int Kloc, int lda, int ldb, int N)
{
    extern __shared__ char smem_raw[];
    uint32_t sbase = smem_u32(smem_raw);
    uint32_t abase = (sbase + 1023u) & ~1023u;

    int tid = threadIdx.x;
    int lane = tid & 31;
    int wid = tid >> 5;
    int warp_m = wid & 1;
    int warp_n = wid >> 1;
    int row0 = blockIdx.y * 64;
    int col0 = blockIdx.x * 64;
    int koff = kbase + blockIdx.z * Kloc;
    int NC = Kloc >> 6;

    cudaGridDependencySynchronize();   // A activations come from predecessor

    float acc[2][2][4];
#pragma unroll
    for (int i = 0; i < 2; i++)
#pragma unroll
        for (int j = 0; j < 2; j++)
#pragma unroll
            for (int q = 0; q < 4; q++) acc[i][j][q] = 0.0f;

    auto load_chunk = [&](int buf, int k0) {
        uint32_t bb = abase + buf * GBUF_BYTES;
#pragma unroll
        for (int i = 0; i < 2; i++) {
            int u = tid + i * 256;
            int r = u >> 3, ch = u & 7;
            uint32_t soff = SW128((uint32_t)(r * 128 + ch * 16));
            size_t goA = (size_t)(row0 + r) * lda + koff + k0 + ch * 8;
            size_t goB = (size_t)(col0 + r) * ldb + koff + k0 + ch * 8;
            CP_ASYNC16(bb + soff,          Ahi + goA);
            CP_ASYNC16(bb + 8192 + soff,   Alo + goA);
            CP_ASYNC16(bb + 16384 + soff,  Bhi + goB);
            CP_ASYNC16(bb + 24576 + soff,  Blo + goB);
        }
    };

    load_chunk(0, 0);
    CP_COMMIT();
    load_chunk(1, 64);
    CP_COMMIT();

    int a_r = warp_m * 32 + (lane & 15);
    int a_csel = (lane >> 4) << 3;
    int b_r = warp_n * 16 + (lane & 7) + ((lane >> 4) << 3);
    int b_csel = ((lane >> 3) & 1) << 3;

    int buf = 0, pbuf = 2;
    for (int c = 0; c < NC; c++) {
        CP_WAIT(GSTAGES - 2);
        __syncthreads();
        if (c + 2 < NC) load_chunk(pbuf, (c + 2) * 64);
        CP_COMMIT();

        uint32_t bb = abase + buf * GBUF_BYTES;
#pragma unroll
        for (int kk = 0; kk < 4; kk++) {
            int k0 = kk * 16;
            uint32_t ah[2][4], al[2][4], bh[4], bl[4];
#pragma unroll
            for (int mf = 0; mf < 2; mf++) {
                uint32_t off = SW128((uint32_t)((a_r + mf * 16) * 128 + (k0 + a_csel) * 2));
                LDSM4(ah[mf], bb + off);
                LDSM4(al[mf], bb + 8192 + off);
            }
            {
                uint32_t off = SW128((uint32_t)(b_r * 128 + (k0 + b_csel) * 2));
                LDSM4(bh, bb + 16384 + off);
                LDSM4(bl, bb + 24576 + off);
            }
#pragma unroll
            for (int mf = 0; mf < 2; mf++) {
#pragma unroll
                for (int nf = 0; nf < 2; nf++) {
                    MMA16816(acc[mf][nf], ah[mf], bh[2 * nf], bh[2 * nf + 1]);
                    MMA16816(acc[mf][nf], ah[mf], bl[2 * nf], bl[2 * nf + 1]);
                    MMA16816(acc[mf][nf], al[mf], bh[2 * nf], bh[2 * nf + 1]);
                }
            }
        }
        buf = (buf == GSTAGES - 1) ? 0 : buf + 1;
        pbuf = (pbuf == GSTAGES - 1) ? 0 : pbuf + 1;
    }

    float* Cz = C + (size_t)blockIdx.z * Bx * N;
    int gid = lane >> 2, tig = lane & 3;
#pragma unroll
    for (int mf = 0; mf < 2; mf++) {
#pragma unroll
        for (int nf = 0; nf < 2; nf++) {
            int r = row0 + warp_m * 32 + mf * 16 + gid;
            int cc = col0 + warp_n * 16 + nf * 8 + tig * 2;
            float2 o0 = { acc[mf][nf][0], acc[mf][nf][1] };
            float2 o1 = { acc[mf][nf][2], acc[mf][nf][3] };
            *(float2*)&Cz[(size_t)r * N + cc] = o0;
            *(float2*)&Cz[(size_t)(r + 8) * N + cc] = o1;
        }
    }
}

// ================= prep kernels (main + side branch) =================
__device__ void tsplit_block(const float* __restrict__ W, int K, int N,
                             __nv_bfloat16* __restrict__ Ohi, __nv_bfloat16* __restrict__ Olo,
                             int local) {
    __shared__ float t[32][33];
    int ktiles = K >> 5;
    int kt = local % ktiles, nt = local / ktiles;
    int k0 = kt * 32, n0 = nt * 32;
    int tx = threadIdx.x & 31, ty = threadIdx.x >> 5;
    for (int i = ty; i < 32; i += 8)
        t[i][tx] = W[(size_t)(k0 + i) * N + n0 + tx];
    __syncthreads();
    for (int i = ty; i < 32; i += 8) {
        float v = t[tx][i];
        size_t o = (size_t)(n0 + i) * K + k0 + tx;
        __nv_bfloat16 h, l;
        split2(v, &h, &l);
        Ohi[o] = h; Olo[o] = l;
    }
}

__global__ void __launch_bounds__(256) k_prep_main(
    const unsigned char* __restrict__ dones_raw,
    const float* __restrict__ dp,
    const float* __restrict__ obs,
    const float* __restrict__ bw1, const float* __restrict__ bw2) {
    int bid = blockIdx.x, tid = threadIdx.x;
    if (bid == 0) {
        __shared__ int mode;
        if (tid == 0) {
            bool nzoff = false, floatlike = true, anynz = false;
            for (int i = 0; i < Bx; i++) {
                unsigned char v = dones_raw[i];
                if (v) {
                    anynz = true;
                    int r = i & 3;
                    if (r != 0) nzoff = true;
                    bool okf = (r == 2 && v == 0x80) || (r == 3 && v == 0x3F);
                    if (!okf) floatlike = false;
                }
            }
            mode = (nzoff && floatlike && anynz) ? 2 : (nzoff ? 0 : 1);
        }
        __syncthreads();
        int b = tid, m = mode, v;
        if (m == 0)      v = (dones_raw[b] != 0);
        else if (m == 1) v = (((const int*)dones_raw)[b] != 0);
        else             v = (((const float*)dones_raw)[b] != 0.0f);
        g_dones[b] = v;
    } else if (bid < 10) {
        int s = (bid - 1) * 256 + tid;
        if (s < SYNCHx) {
            float c = fminf(fmaxf(dp[s], 0.0f), 4.0f);
            float sum = 0.0f;
            for (int m = 0; m < Mx; m++) {
                float v = __expf(-(float)(Mx - 1 - m) * c);
                g_decay[m * SYNCHx + s] = v;
                sum += v;
            }
            g_invden[s] = rsqrtf(sum);
            int i = 0, base = 0;
            while (s >= base + (NSYx - i)) { base += NSYx - i; i++; }
            g_tri_i[s] = i;
            g_tri_j[s] = i + (s - base);
        }
    } else if (bid < 266) {
        int i = (bid - 10) * 256 + tid;
        split2(obs[i], &g_obshi[i], &g_obslo[i]);
    } else if (bid < 522) {
        tsplit_block(bw1, 256, 1024, g_wb1hi, g_wb1lo, bid - 266);
    } else {
        tsplit_block(bw2, 512, 1024, g_wb2hi, g_wb2lo, bid - 522);
    }
}

__global__ void __launch_bounds__(256) k_prep_side(
    const float* __restrict__ nw1, const float* __restrict__ nw2,
    const float* __restrict__ sw1, const float* __restrict__ sw2) {
    int bid = blockIdx.x, tid = threadIdx.x;
    if (bid < 4096) {
        int idx = bid * 256 + tid;
        int d = idx >> 10, hm = idx & 1023;
        int h = hm >> 5, m = hm & 31;
        float v = nw1[(m * 32 + h) * Dx + d];
        split2(v, &g_w1bh[idx], &g_w1bl[idx]);
        if (idx < Dx * 32) {
            int d2 = idx >> 5, hc = idx & 31;
            g_w2t[idx] = nw2[hc * Dx + d2];
        }
    } else if (bid < 7168) {
        tsplit_block(sw1, 1536, 2048, g_ws1hi, g_ws1lo, bid - 4096);
    } else {
        tsplit_block(sw2, 1024, 2048, g_ws2hi, g_ws2lo, bid - 7168);
    }
}

// ====== GLU + LN (sums KS split-K partials + bias) -> bf16 split ======
__global__ void __launch_bounds__(1024) k_gluln_split(
    const float* __restrict__ y, int halfN, int KS,
    const float* __restrict__ bias,
    const float* __restrict__ sc, const float* __restrict__ bi,
    __nv_bfloat16* __restrict__ ohi, __nv_bfloat16* __restrict__ olo,
    int ostride, int gather,
    const float* __restrict__ at_in,
    const float* __restrict__ start_at) {
    __shared__ float red_s[32], red_q[32];
    int row = blockIdx.x, tid = threadIdx.x;
    int nw = blockDim.x >> 5;
    size_t rstride = (size_t)Bx * 2 * halfN;
    const float* yr = y + (size_t)row * 2 * halfN;
    int c = tid;
    cudaGridDependencySynchronize();
    float a = bias[c];
    float g = bias[halfN + c];
    for (int z = 0; z < KS; z++) {
        a += yr[z * rstride + c];
        g += yr[z * rstride + halfN + c];
    }
    float val = a * sigf(g);
    float sum = val, sq = val * val;
#pragma unroll
    for (int o = 16; o > 0; o >>= 1) {
        sum += __shfl_xor_sync(0xffffffffu, sum, o);
        sq  += __shfl_xor_sync(0xffffffffu, sq, o);
    }
    int w = tid >> 5;
    if ((tid & 31) == 0) { red_s[w] = sum; red_q[w] = sq; }
    __syncthreads();
    if (tid == 0) {
        float ts = 0.0f, tq = 0.0f;
        for (int i = 0; i < nw; i++) { ts += red_s[i]; tq += red_q[i]; }
        red_s[0] = ts; red_q[0] = tq;
    }
    __syncthreads();
    float invN = 1.0f / (float)halfN;
    float mean = red_s[0] * invN;
    float var = red_q[0] * invN - mean * mean;
    float inv = rsqrtf(var + 1e-6f);
    {
        float o_ = (val - mean) * inv * sc[c] + bi[c];
        size_t o = (size_t)row * ostride + c;
        split2(o_, &ohi[o], &olo[o]);
    }
    if (gather) {
        bool done = g_dones[row] != 0;
        for (int cc = tid; cc < Dx; cc += blockDim.x) {
            float v2 = done ? start_at[cc * 32 + 31]
                            : at_in[((size_t)(row * Dx + cc)) * 32 + 31];
            size_t o = (size_t)row * ostride + halfN + cc;
            split2(v2, &ohi[o], &olo[o]);
        }
    }
}

// GLU + LN -> fp32 contiguous (h_st[i]); blockDim==halfN
__global__ void __launch_bounds__(1024) k_gluln_f32(
    const float* __restrict__ y, int halfN, int KS,
    const float* __restrict__ bias,
    const float* __restrict__ sc, const float* __restrict__ bi,
    float* __restrict__ out) {
    __shared__ float red_s[32], red_q[32];
    int row = blockIdx.x, tid = threadIdx.x;
    int nw = blockDim.x >> 5;
    size_t rstride = (size_t)Bx * 2 * halfN;
    const float* yr = y + (size_t)row * 2 * halfN;
    int c = tid;
    cudaGridDependencySynchronize();
    float a = bias[c];
    float g = bias[halfN + c];
    for (int z = 0; z < KS; z++) {
        a += yr[z * rstride + c];
        g += yr[z * rstride + halfN + c];
    }
    float val = a * sigf(g);
    float sum = val, sq = val * val;
#pragma unroll
    for (int o = 16; o > 0; o >>= 1) {
        sum += __shfl_xor_sync(0xffffffffu, sum, o);
        sq  += __shfl_xor_sync(0xffffffffu, sq, o);
    }
    int w = tid >> 5;
    if ((tid & 31) == 0) { red_s[w] = sum; red_q[w] = sq; }
    __syncthreads();
    if (tid == 0) {
        float ts = 0.0f, tq = 0.0f;
        for (int i = 0; i < nw; i++) { ts += red_s[i]; tq += red_q[i]; }
        red_s[0] = ts; red_q[0] = tq;
    }
    __syncthreads();
    float invN = 1.0f / (float)halfN;
    float mean = red_s[0] * invN;
    float var = red_q[0] * invN - mean * mean;
    float inv = rsqrtf(var + 1e-6f);
    out[(size_t)row * halfN + c] = (val - mean) * inv * sc[c] + bi[c];
}

// ================= NLM via tensor cores (one d per block) =================
template<int IT>
__global__ void __launch_bounds__(256) k_nlm_tc(
    const float* __restrict__ st_in, const float* __restrict__ start_st,
    const float* __restrict__ b1, const float* __restrict__ T1,
    const float* __restrict__ b2, const float* __restrict__ T2) {
    __shared__ __align__(16) uint8_t Sh[16384], Sl[16384];
    __shared__ __align__(16) uint8_t Wh[2048], Wl[2048];
    __shared__ float w2s[32], b1s[32], b2s[2], invT[2];
    int tid = threadIdx.x;
    int lane = tid & 31;
    int w = tid >> 5;
    int d = blockIdx.x;

    // independent prologue: W tiles + small params (written by prep_side long ago)
    if (tid < 128) {
        uint4 vh = ((const uint4*)(g_w1bh + (size_t)d * 1024))[tid];
        uint4 vl = ((const uint4*)(g_w1bl + (size_t)d * 1024))[tid];
        uint32_t off = (uint32_t)tid * 16;
        uint32_t so = SW64(off);
        *(uint4*)(Wh + so) = vh;
        *(uint4*)(Wl + so) = vl;
    }
    if (tid < 32) { w2s[tid] = g_w2t[d * 32 + tid]; b1s[tid] = b1[d * 32 + tid]; }
    if (tid < 2)  b2s[tid] = b2[d * 2 + tid];
    if (tid == 0) { invT[0] = 1.0f / T1[0]; invT[1] = 1.0f / T2[0]; }

    cudaGridDependencySynchronize();   // g_hst[IT] comes from predecessor

    // S tile: row b = tid, 32 k-cols, window select, bf16 hi/lo
    {
        int b = tid;
        const float* stp = g_dones[b] ? (start_st + d * 32)
                                      : (st_in + ((size_t)(b << 10) + d) * 32);
        float sar[32];
#pragma unroll
        for (int q = 0; q < 8; q++) {
            float4 t4 = ((const float4*)stp)[q];
            sar[q * 4 + 0] = t4.x; sar[q * 4 + 1] = t4.y;
            sar[q * 4 + 2] = t4.z; sar[q * 4 + 3] = t4.w;
        }
        float vals[32];
#pragma unroll
        for (int k = 0; k < 31 - IT; k++) vals[k] = sar[k + IT + 1];
#pragma unroll
        for (int j = 0; j <= IT; j++) vals[31 - IT + j] = g_hst[j][(size_t)b * 1024 + d];
#pragma unroll
        for (int q = 0; q < 4; q++) {
            uint32_t ph[4], pl[4];
#pragma unroll
            for (int p = 0; p < 4; p++)
                split_pack(vals[q * 8 + p * 2], vals[q * 8 + p * 2 + 1], ph[p], pl[p]);
            uint32_t off = (uint32_t)(b * 64 + q * 16);
            uint32_t so = SW64(off);
            *(uint4*)(Sh + so) = make_uint4(ph[0], ph[1], ph[2], ph[3]);
            *(uint4*)(Sl + so) = make_uint4(pl[0], pl[1], pl[2], pl[3]);
        }
    }
    __syncthreads();

    uint32_t sbh = smem_u32(Sh), sbl = smem_u32(Sl);
    uint32_t wbh = smem_u32(Wh), wbl = smem_u32(Wl);

    float acc[2][4][4];
#pragma unroll
    for (int mt = 0; mt < 2; mt++)
#pragma unroll
        for (int f = 0; f < 4; f++)
#pragma unroll
            for (int q = 0; q < 4; q++) acc[mt][f][q] = 0.0f;

#pragma unroll
    for (int ks = 0; ks < 2; ks++) {
        int cbA = ks * 32 + ((lane >> 4) << 4);
        uint32_t ah[2][4], al[2][4];
#pragma unroll
        for (int mt = 0; mt < 2; mt++) {
            int row = w * 32 + mt * 16 + (lane & 15);
            uint32_t off = SW64((uint32_t)(row * 64 + cbA));
            LDSM4(ah[mt], sbh + off);
            LDSM4(al[mt], sbl + off);
        }
        uint32_t bh[8], bl[8];
        int cbB = ks * 32 + (((lane >> 3) & 1) << 4);
#pragma unroll
        for (int g = 0; g < 2; g++) {
            int rowb = g * 16 + (lane & 7) + ((lane >> 4) << 3);
            uint32_t off = SW64((uint32_t)(rowb * 64 + cbB));
            LDSM4(bh + g * 4, wbh + off);
            LDSM4(bl + g * 4, wbl + off);
        }
#pragma unroll
        for (int mt = 0; mt < 2; mt++) {
#pragma unroll
            for (int f = 0; f < 4; f++) {
                MMA16816(acc[mt][f], ah[mt], bh[2 * f], bh[2 * f + 1]);
                MMA16816(acc[mt][f], ah[mt], bl[2 * f], bl[2 * f + 1]);
                MMA16816(acc[mt][f], al[mt], bh[2 * f], bh[2 * f + 1]);
            }
        }
    }

    // epilogue: layer 2 (16 -> 2) + write results
    int gid = lane >> 2, tig = lane & 3;
    float iT1 = invT[0], iT2 = invT[1];
#pragma unroll
    for (int mt = 0; mt < 2; mt++) {
#pragma unroll
        for (int rsel = 0; rsel < 2; rsel++) {
            float y0 = 0.0f, y1 = 0.0f;
#pragma unroll
            for (int f = 0; f < 2; f++) {
#pragma unroll
                for (int c2 = 0; c2 < 2; c2++) {
                    int h = f * 8 + tig * 2 + c2;
                    float xv = acc[mt][f][rsel * 2 + c2] + b1s[h];
                    float gv = acc[mt][f + 2][rsel * 2 + c2] + b1s[h + 16];
                    float u = (xv * iT1) * sigf(gv * iT1);
                    y0 += u * w2s[h * 2 + 0];
                    y1 += u * w2s[h * 2 + 1];
                }
            }
            y0 += __shfl_xor_sync(0xffffffffu, y0, 1);
            y0 += __shfl_xor_sync(0xffffffffu, y0, 2);
            y1 += __shfl_xor_sync(0xffffffffu, y1, 1);
            y1 += __shfl_xor_sync(0xffffffffu, y1, 2);
            if (tig == 0) {
                float fy0 = y0 + b2s[0];
                float fy1 = y1 + b2s[1];
                float r = (fy0 * iT2) * sigf(fy1 * iT2);
                int brow = w * 32 + mt * 16 + rsel * 8 + gid;
                g_hat[IT][(size_t)d * Bx + brow] = r;
                if (IT < 3) {
                    __nv_bfloat16 hh, ll;
                    split2(r, &hh, &ll);
                    size_t o = (size_t)brow * (DINx + Dx) + DINx + d;
                    g_prehi[o] = hh; g_prelo[o] = ll;
                }
            }
        }
    }
}

// ================= final assembly + synchrony =================
__global__ void __launch_bounds__(256) k_fin(
    float* __restrict__ out,
    const float* __restrict__ st_in, const float* __restrict__ at_in,
    const float* __restrict__ start_st, const float* __restrict__ start_at) {
    int tid = threadIdx.x;
    cudaGridDependencySynchronize();
    if (blockIdx.x < 1024) {
        __shared__ float hsm[4][32][9];
        int local = blockIdx.x;
        int dt = local & 127, bt = local >> 7;
        int d0 = dt * 8, b0 = bt * 32;
        {
            int j = tid >> 6, rem = tid & 63, bl = rem >> 1, hf = rem & 1;
            float4 hv = *(const float4*)&g_hst[j][(size_t)(b0 + bl) * Dx + d0 + hf * 4];
            hsm[j][bl][hf * 4 + 0] = hv.x;
            hsm[j][bl][hf * 4 + 1] = hv.y;
            hsm[j][bl][hf * 4 + 2] = hv.z;
            hsm[j][bl][hf * 4 + 3] = hv.w;
        }
        __syncthreads();
        int w = tid >> 5, lane = tid & 31;
        int d = d0 + w, b = b0 + lane;
        bool done = g_dones[b] != 0;
        const float* stp = done ? (start_st + d * 32) : (st_in + ((size_t)(b << 10) + d) * 32);
        const float* atp = done ? (start_at + d * 32) : (at_in + ((size_t)(b << 10) + d) * 32);
        float so[32], ao[32];
#pragma unroll
        for (int q = 1; q < 8; q++) {
            float4 t4 = ((const float4*)stp)[q];
            so[q * 4 - 4] = t4.x; so[q * 4 - 3] = t4.y; so[q * 4 - 2] = t4.z; so[q * 4 - 1] = t4.w;
            float4 u4 = ((const float4*)atp)[q];
            ao[q * 4 - 4] = u4.x; ao[q * 4 - 3] = u4.y; ao[q * 4 - 2] = u4.z; ao[q * 4 - 1] = u4.w;
        }
#pragma unroll
        for (int j = 0; j < 4; j++) {
            so[28 + j] = hsm[j][lane][w];
            ao[28 + j] = g_hat[j][(size_t)d * Bx + b];
        }
        float* o1 = out + ((size_t)(b << 10) + d) * 32;
        float* o2 = o1 + BDMx;
#pragma unroll
        for (int q = 0; q < 8; q++) {
            float4 v1 = { so[q * 4], so[q * 4 + 1], so[q * 4 + 2], so[q * 4 + 3] };
            float4 v2 = { ao[q * 4], ao[q * 4 + 1], ao[q * 4 + 2], ao[q * 4 + 3] };
            ((float4*)o1)[q] = v1;
            ((float4*)o2)[q] = v2;
        }
    } else {
        __shared__ float S[Mx * NSYx];
        int b = blockIdx.x - 1024;
        bool done = g_dones[b] != 0;
        float* outs = out + 2 * (size_t)BDMx;
        for (int t = tid; t < Mx * NSYx; t += 256) {
            int m = t & 31, j = t >> 5;
            int dd = Dx - NSYx + j;
            float val;
            if (m < 28)
                val = done ? start_at[dd * 32 + m + 4]
                           : at_in[((size_t)(b * Dx + dd)) * 32 + m + 4];
            else
                val = g_hat[m - 28][(size_t)dd * Bx + b];
            S[m * NSYx + j] = val;
        }
        __syncthreads();
        for (int s = tid; s < SYNCHx; s += 256) {
            int ti = g_tri_i[s], tj = g_tri_j[s];
            float acc = 0.0f;
#pragma unroll
            for (int m = 0; m < Mx; m++)
                acc += g_decay[m * SYNCHx + s] * S[m * NSYx + ti] * S[m * NSYx + tj];
            outs[(size_t)b * SYNCHx + s] = acc * g_invden[s];
        }
    }
}

// ================= PDL launch helper =================
template <typename F, typename... Args>
static inline void pdl_launch(F* f, dim3 g, dim3 b, size_t shm, Args... args) {
    cudaLaunchConfig_t cfg = {};
    cfg.gridDim = g;
    cfg.blockDim = b;
    cfg.dynamicSmemBytes = shm;
    cfg.stream = 0;
    cudaLaunchAttribute at[1];
    at[0].id = cudaLaunchAttributeProgrammaticStreamSerialization;
    at[0].val.programmaticStreamSerializationAllowed = 1;
    cfg.attrs = at;
    cfg.numAttrs = 1;
    cudaLaunchKernelEx(&cfg, f, args...);
}

// =====================================================================
extern "C" void kernel_launch(void* const* d_in, const int* in_sizes, int n_in,
                              void* d_out, int out_size) {
    (void)in_sizes; (void)n_in; (void)out_size;
    const float* obs      = (const float*)d_in[0];
    const unsigned char* dones_raw = (const unsigned char*)d_in[1];
    const float* st_in    = (const float*)d_in[3];
    const float* at_in    = (const float*)d_in[4];
    const float* start_st = (const float*)d_in[5];
    const float* start_at = (const float*)d_in[6];
    const float* bb_w1    = (const float*)d_in[7];
    const float* bb_b1    = (const float*)d_in[8];
    const float* ln1s     = (const float*)d_in[9];
    const float* ln1b     = (const float*)d_in[10];
    const float* bb_w2    = (const float*)d_in[11];
    const float* bb_b2    = (const float*)d_in[12];
    const float* ln2s     = (const float*)d_in[13];
    const float* ln2b     = (const float*)d_in[14];
    const float* syn_w1   = (const float*)d_in[15];
    const float* syn_b1   = (const float*)d_in[16];
    const float* sln1s    = (const float*)d_in[17];
    const float* sln1b    = (const float*)d_in[18];
    const float* syn_w2   = (const float*)d_in[19];
    const float* syn_b2   = (const float*)d_in[20];
    const float* sln2s    = (const float*)d_in[21];
    const float* sln2b    = (const float*)d_in[22];
    const float* nlm1_w   = (const float*)d_in[23];
    const float* nlm1_b   = (const float*)d_in[24];
    const float* nlm1_T   = (const float*)d_in[25];
    const float* nlm2_w   = (const float*)d_in[26];
    const float* nlm2_b   = (const float*)d_in[27];
    const float* nlm2_T   = (const float*)d_in[28];
    const float* decay_p  = (const float*)d_in[29];
    float* out = (float*)d_out;

    void *p_y, *p_hst;
    void *p_obshi, *p_obslo, *p_prehi, *p_prelo, *p_h1hi, *p_h1lo;
    void *p_wb1h, *p_wb1l, *p_wb2h, *p_wb2l, *p_ws1h, *p_ws1l, *p_ws2h, *p_ws2l;
    cudaGetSymbolAddress(&p_y, g_y);
    cudaGetSymbolAddress(&p_hst, g_hst);
    cudaGetSymbolAddress(&p_obshi, g_obshi);  cudaGetSymbolAddress(&p_obslo, g_obslo);
    cudaGetSymbolAddress(&p_prehi, g_prehi);  cudaGetSymbolAddress(&p_prelo, g_prelo);
    cudaGetSymbolAddress(&p_h1hi, g_h1hi);    cudaGetSymbolAddress(&p_h1lo, g_h1lo);
    cudaGetSymbolAddress(&p_wb1h, g_wb1hi);   cudaGetSymbolAddress(&p_wb1l, g_wb1lo);
    cudaGetSymbolAddress(&p_wb2h, g_wb2hi);   cudaGetSymbolAddress(&p_wb2l, g_wb2lo);
    cudaGetSymbolAddress(&p_ws1h, g_ws1hi);   cudaGetSymbolAddress(&p_ws1l, g_ws1lo);
    cudaGetSymbolAddress(&p_ws2h, g_ws2hi);   cudaGetSymbolAddress(&p_ws2l, g_ws2lo);
    float* gy   = (float*)p_y;
    float* ghst = (float*)p_hst;

    static int init_done = 0;
    static cudaStream_t s_side = nullptr;
    static cudaEvent_t ev_fork = nullptr, ev_join = nullptr;
    int gsmem = GSTAGES * GBUF_BYTES + 1024;
    if (!init_done) {
        cudaFuncSetAttribute(k_tgemm, cudaFuncAttributeMaxDynamicSharedMemorySize, gsmem);
        cudaStreamCreateWithFlags(&s_side, cudaStreamNonBlocking);
        cudaEventCreateWithFlags(&ev_fork, cudaEventDisableTiming);
        cudaEventCreateWithFlags(&ev_join, cudaEventDisableTiming);
        init_done = 1;
    }

    // fork: side branch preps NLM + synapse weights
    cudaEventRecord(ev_fork, 0);
    cudaStreamWaitEvent(s_side, ev_fork, 0);
    k_prep_side<<<9216, 256, 0, s_side>>>(nlm1_w, nlm2_w, syn_w1, syn_w2);
    cudaEventRecord(ev_join, s_side);

    // main branch: light prep + backbone (chain under PDL)
    k_prep_main<<<1034, 256>>>(dones_raw, decay_p, obs, bb_w1, bb_w2);

    pdl_launch(k_tgemm, dim3(16, 4, 2), dim3(256), (size_t)gsmem,
        (const __nv_bfloat16*)p_obshi, (const __nv_bfloat16*)p_obslo,
        (const __nv_bfloat16*)p_wb1h, (const __nv_bfloat16*)p_wb1l,
        gy, 0, 128, 256, 256, 1024);
    pdl_launch(k_gluln_split, dim3(Bx), dim3(512), (size_t)0,
        (const float*)gy, 512, 2, bb_b1, ln1s, ln1b,
        (__nv_bfloat16*)p_h1hi, (__nv_bfloat16*)p_h1lo, 512, 0,
        (const float*)nullptr, (const float*)nullptr);
    pdl_launch(k_tgemm, dim3(16, 4, 2), dim3(256), (size_t)gsmem,
        (const __nv_bfloat16*)p_h1hi, (const __nv_bfloat16*)p_h1lo,
        (const __nv_bfloat16*)p_wb2h, (const __nv_bfloat16*)p_wb2l,
        gy, 0, 256, 512, 512, 1024);
    pdl_launch(k_gluln_split, dim3(Bx), dim3(512), (size_t)0,
        (const float*)gy, 512, 2, bb_b2, ln2s, ln2b,
        (__nv_bfloat16*)p_prehi, (__nv_bfloat16*)p_prelo, 1536, 1, at_in, start_at);

    // join: synapse + NLM weights ready
    cudaStreamWaitEvent(0, ev_join, 0);

    // hoisted f-part of synapse GEMM1 (iteration-invariant): K=0..512 -> slice 2
    pdl_launch(k_tgemm, dim3(32, 4, 1), dim3(256), (size_t)gsmem,
        (const __nv_bfloat16*)p_prehi, (const __nv_bfloat16*)p_prelo,
        (const __nv_bfloat16*)p_ws1h, (const __nv_bfloat16*)p_ws1l,
        gy + 2 * (size_t)Bx * 2048, 0, 512, 1536, 1536, 2048);

    for (int i = 0; i < ITERSx; i++) {
        // synapse GEMM1, at-part only: K=512..1536, KS=2
        pdl_launch(k_tgemm, dim3(32, 4, 2), dim3(256), (size_t)gsmem,
            (const __nv_bfloat16*)p_prehi, (const __nv_bfloat16*)p_prelo,
            (const __nv_bfloat16*)p_ws1h, (const __nv_bfloat16*)p_ws1l,
            gy, 512, 512, 1536, 1536, 2048);
        pdl_launch(k_gluln_split, dim3(Bx), dim3(1024), (size_t)0,
            (const float*)gy, 1024, 3, syn_b1, sln1s, sln1b,
            (__nv_bfloat16*)p_h1hi, (__nv_bfloat16*)p_h1lo, 1024, 0,
            (const float*)nullptr, (const float*)nullptr);
        // synapse GEMM2 K=1024, KS=2
        pdl_launch(k_tgemm, dim3(32, 4, 2), dim3(256), (size_t)gsmem,
            (const __nv_bfloat16*)p_h1hi, (const __nv_bfloat16*)p_h1lo,
            (const __nv_bfloat16*)p_ws2h, (const __nv_bfloat16*)p_ws2l,
            gy, 0, 512, 1024, 1024, 2048);
        pdl_launch(k_gluln_f32, dim3(Bx), dim3(1024), (size_t)0,
            (const float*)gy, 1024, 2, syn_b2, sln2s, sln2b,
            ghst + (size_t)i * BDx);
        switch (i) {
            case 0: pdl_launch(k_nlm_tc<0>, dim3(1024), dim3(256), (size_t)0,
                        st_in, start_st, nlm1_b, nlm1_T, nlm2_b, nlm2_T); break;
            case 1: pdl_launch(k_nlm_tc<1>, dim3(1024), dim3(256), (size_t)0,
                        st_in, start_st, nlm1_b, nlm1_T, nlm2_b, nlm2_T); break;
            case 2: pdl_launch(k_nlm_tc<2>, dim3(1024), dim3(256), (size_t)0,
                        st_in, start_st, nlm1_b, nlm1_T, nlm2_b, nlm2_T); break;
            case 3: pdl_launch(k_nlm_tc<3>, dim3(1024), dim3(256), (size_t)0,
                        st_in, start_st, nlm1_b, nlm1_T, nlm2_b, nlm2_T); break;
        }
    }

    pdl_launch(k_fin, dim3(1024 + Bx), dim3(256), (size_t)0,
        out, st_in, at_in, start_st, start_at);
}

// round 14
// speedup vs baseline: 1.4049x; 1.4049x over previous
#include <cuda_runtime.h>
#include <cuda_bf16.h>
#include <math.h>
#include <stdint.h>

#define Bx    256
#define OBSx  256
#define DINx  512
#define Dx    1024
#define Mx    32
#define HIDx  16
#define NSYx  64
#define ITERSx 4
#define SYNCHx 2080
#define BDx   (Bx * Dx)          // 262144
#define BDMx  (Bx * Dx * Mx)     // 8388608

// ---------------- scratch (static device globals) ----------------
__device__ float g_y[4 * Bx * 2 * Dx];               // split-K partial slices
__device__ __align__(16) __nv_bfloat16 g_w1bh[Dx * 1024];  // [d][h*32+m] bf16 hi
__device__ __align__(16) __nv_bfloat16 g_w1bl[Dx * 1024];  // [d][h*32+m] bf16 lo
__device__ float g_w2t[Dx * 32];
__device__ float g_decay[Mx * SYNCHx];
__device__ float g_invden[SYNCHx];
__device__ int   g_tri_i[SYNCHx];
__device__ int   g_tri_j[SYNCHx];
__device__ int   g_dones[Bx];
__device__ __align__(16) float g_hst[ITERSx][BDx];   // [i][b*1024+d]
__device__ __align__(16) float g_hat[ITERSx][BDx];   // [i][d*256+b]

__device__ __align__(256) __nv_bfloat16 g_obshi[Bx * OBSx];
__device__ __align__(256) __nv_bfloat16 g_obslo[Bx * OBSx];
__device__ __align__(256) __nv_bfloat16 g_prehi[Bx * (DINx + Dx)];
__device__ __align__(256) __nv_bfloat16 g_prelo[Bx * (DINx + Dx)];
__device__ __align__(256) __nv_bfloat16 g_h1hi[Bx * Dx];
__device__ __align__(256) __nv_bfloat16 g_h1lo[Bx * Dx];
__device__ __align__(256) __nv_bfloat16 g_wb1hi[1024 * 256];
__device__ __align__(256) __nv_bfloat16 g_wb1lo[1024 * 256];
__device__ __align__(256) __nv_bfloat16 g_wb2hi[1024 * 512];
__device__ __align__(256) __nv_bfloat16 g_wb2lo[1024 * 512];
__device__ __align__(256) __nv_bfloat16 g_ws1hi[2048 * 1536];
__device__ __align__(256) __nv_bfloat16 g_ws1lo[2048 * 1536];
__device__ __align__(256) __nv_bfloat16 g_ws2hi[2048 * 1024];
__device__ __align__(256) __nv_bfloat16 g_ws2lo[2048 * 1024];

__device__ __forceinline__ float sigf(float x) {
    return __fdividef(1.0f, 1.0f + __expf(-x));
}
__device__ __forceinline__ void split2(float v, __nv_bfloat16* h, __nv_bfloat16* l) {
    __nv_bfloat16 hh = __float2bfloat16(v);
    *h = hh;
    *l = __float2bfloat16(v - __bfloat162float(hh));
}
__device__ __forceinline__ void split_pack(float v0, float v1, uint32_t& ph, uint32_t& pl) {
    __nv_bfloat16 h0 = __float2bfloat16(v0);
    __nv_bfloat16 h1 = __float2bfloat16(v1);
    __nv_bfloat16 l0 = __float2bfloat16(v0 - __bfloat162float(h0));
    __nv_bfloat16 l1 = __float2bfloat16(v1 - __bfloat162float(h1));
    unsigned short u0, u1;
    memcpy(&u0, &h0, 2); memcpy(&u1, &h1, 2);
    ph = (uint32_t)u0 | ((uint32_t)u1 << 16);
    memcpy(&u0, &l0, 2); memcpy(&u1, &l1, 2);
    pl = (uint32_t)u0 | ((uint32_t)u1 << 16);
}

// ================= PTX helpers =================
__device__ __forceinline__ uint32_t smem_u32(const void* p) {
    uint32_t a;
    asm("{ .reg .u64 t; cvta.to.shared.u64 t, %1; cvt.u32.u64 %0, t; }" : "=r"(a) : "l"(p));
    return a;
}
#define SW128(off) ((off) ^ (((off) >> 3) & 0x70))
#define SW64(off)  ((off) ^ (((off) >> 3) & 0x30))
#define CP_ASYNC16(dst, src) \
    asm volatile("cp.async.cg.shared.global [%0], [%1], 16;" :: "r"(dst), "l"(src))
#define CP_COMMIT()  asm volatile("cp.async.commit_group;" ::: "memory")
#define CP_WAIT(n)   asm volatile("cp.async.wait_group %0;" :: "n"(n) : "memory")
#define LDSM4(r, addr) \
    asm volatile("ldmatrix.sync.aligned.m8n8.x4.shared.b16 {%0,%1,%2,%3}, [%4];" \
        : "=r"((r)[0]), "=r"((r)[1]), "=r"((r)[2]), "=r"((r)[3]) : "r"(addr))
#define MMA16816(acc, a, b0, b1) \
    asm volatile("mma.sync.aligned.m16n8k16.row.col.f32.bf16.bf16.f32 " \
        "{%0,%1,%2,%3}, {%4,%5,%6,%7}, {%8,%9}, {%0,%1,%2,%3};" \
        : "+f"((acc)[0]), "+f"((acc)[1]), "+f"((acc)[2]), "+f"((acc)[3]) \
        : "r"((a)[0]), "r"((a)[1]), "r"((a)[2]), "r"((a)[3]), "r"(b0), "r"(b1))

// ================= split-bf16 HMMA GEMM, split-K with K-base offset =========
#define GBUF_BYTES 32768
#define GSTAGES 3
__global__ void __launch_bounds__(256) k_tgemm(
    const __nv_bfloat16* __restrict__ Ahi, const __nv_bfloat16* __restrict__ Alo,
    const __nv_bfloat16* __restrict__ Bhi, const __nv_bfloat16* __restrict__ Blo,
    float* __restrict__ C, int kbase, int Kloc, int lda, int ldb, int N)
{
    extern __shared__ char smem_raw[];
    uint32_t sbase = smem_u32(smem_raw);
    uint32_t abase = (sbase + 1023u) & ~1023u;

    int tid = threadIdx.x;
    int lane = tid & 31;
    int wid = tid >> 5;
    int warp_m = wid & 1;
    int warp_n = wid >> 1;
    int row0 = blockIdx.y * 64;
    int col0 = blockIdx.x * 64;
    int koff = kbase + blockIdx.z * Kloc;
    int NC = Kloc >> 6;

    float acc[2][2][4];
#pragma unroll
    for (int i = 0; i < 2; i++)
#pragma unroll
        for (int j = 0; j < 2; j++)
#pragma unroll
            for (int q = 0; q < 4; q++) acc[i][j][q] = 0.0f;

    auto load_chunk = [&](int buf, int k0) {
        uint32_t bb = abase + buf * GBUF_BYTES;
#pragma unroll
        for (int i = 0; i < 2; i++) {
            int u = tid + i * 256;
            int r = u >> 3, ch = u & 7;
            uint32_t soff = SW128((uint32_t)(r * 128 + ch * 16));
            size_t goA = (size_t)(row0 + r) * lda + koff + k0 + ch * 8;
            size_t goB = (size_t)(col0 + r) * ldb + koff + k0 + ch * 8;
            CP_ASYNC16(bb + soff,          Ahi + goA);
            CP_ASYNC16(bb + 8192 + soff,   Alo + goA);
            CP_ASYNC16(bb + 16384 + soff,  Bhi + goB);
            CP_ASYNC16(bb + 24576 + soff,  Blo + goB);
        }
    };

    load_chunk(0, 0);
    CP_COMMIT();
    load_chunk(1, 64);
    CP_COMMIT();

    int a_r = warp_m * 32 + (lane & 15);
    int a_csel = (lane >> 4) << 3;
    int b_r = warp_n * 16 + (lane & 7) + ((lane >> 4) << 3);
    int b_csel = ((lane >> 3) & 1) << 3;

    int buf = 0, pbuf = 2;
    for (int c = 0; c < NC; c++) {
        CP_WAIT(GSTAGES - 2);
        __syncthreads();
        if (c + 2 < NC) load_chunk(pbuf, (c + 2) * 64);
        CP_COMMIT();

        uint32_t bb = abase + buf * GBUF_BYTES;
#pragma unroll
        for (int kk = 0; kk < 4; kk++) {
            int k0 = kk * 16;
            uint32_t ah[2][4], al[2][4], bh[4], bl[4];
#pragma unroll
            for (int mf = 0; mf < 2; mf++) {
                uint32_t off = SW128((uint32_t)((a_r + mf * 16) * 128 + (k0 + a_csel) * 2));
                LDSM4(ah[mf], bb + off);
                LDSM4(al[mf], bb + 8192 + off);
            }
            {
                uint32_t off = SW128((uint32_t)(b_r * 128 + (k0 + b_csel) * 2));
                LDSM4(bh, bb + 16384 + off);
                LDSM4(bl, bb + 24576 + off);
            }
#pragma unroll
            for (int mf = 0; mf < 2; mf++) {
#pragma unroll
                for (int nf = 0; nf < 2; nf++) {
                    MMA16816(acc[mf][nf], ah[mf], bh[2 * nf], bh[2 * nf + 1]);
                    MMA16816(acc[mf][nf], ah[mf], bl[2 * nf], bl[2 * nf + 1]);
                    MMA16816(acc[mf][nf], al[mf], bh[2 * nf], bh[2 * nf + 1]);
                }
            }
        }
        buf = (buf == GSTAGES - 1) ? 0 : buf + 1;
        pbuf = (pbuf == GSTAGES - 1) ? 0 : pbuf + 1;
    }

    float* Cz = C + (size_t)blockIdx.z * Bx * N;
    int gid = lane >> 2, tig = lane & 3;
#pragma unroll
    for (int mf = 0; mf < 2; mf++) {
#pragma unroll
        for (int nf = 0; nf < 2; nf++) {
            int r = row0 + warp_m * 32 + mf * 16 + gid;
            int cc = col0 + warp_n * 16 + nf * 8 + tig * 2;
            float2 o0 = { acc[mf][nf][0], acc[mf][nf][1] };
            float2 o1 = { acc[mf][nf][2], acc[mf][nf][3] };
            *(float2*)&Cz[(size_t)r * N + cc] = o0;
            *(float2*)&Cz[(size_t)(r + 8) * N + cc] = o1;
        }
    }
}

// ================= prep kernels (main + side branch) =================
__device__ void tsplit_block(const float* __restrict__ W, int K, int N,
                             __nv_bfloat16* __restrict__ Ohi, __nv_bfloat16* __restrict__ Olo,
                             int local) {
    __shared__ float t[32][33];
    int ktiles = K >> 5;
    int kt = local % ktiles, nt = local / ktiles;
    int k0 = kt * 32, n0 = nt * 32;
    int tx = threadIdx.x & 31, ty = threadIdx.x >> 5;
    for (int i = ty; i < 32; i += 8)
        t[i][tx] = W[(size_t)(k0 + i) * N + n0 + tx];
    __syncthreads();
    for (int i = ty; i < 32; i += 8) {
        float v = t[tx][i];
        size_t o = (size_t)(n0 + i) * K + k0 + tx;
        __nv_bfloat16 h, l;
        split2(v, &h, &l);
        Ohi[o] = h; Olo[o] = l;
    }
}

__global__ void __launch_bounds__(256) k_prep_main(
    const unsigned char* __restrict__ dones_raw,
    const float* __restrict__ dp,
    const float* __restrict__ obs,
    const float* __restrict__ bw1, const float* __restrict__ bw2) {
    int bid = blockIdx.x, tid = threadIdx.x;
    if (bid == 0) {
        __shared__ int mode;
        if (tid == 0) {
            bool nzoff = false, floatlike = true, anynz = false;
            for (int i = 0; i < Bx; i++) {
                unsigned char v = dones_raw[i];
                if (v) {
                    anynz = true;
                    int r = i & 3;
                    if (r != 0) nzoff = true;
                    bool okf = (r == 2 && v == 0x80) || (r == 3 && v == 0x3F);
                    if (!okf) floatlike = false;
                }
            }
            mode = (nzoff && floatlike && anynz) ? 2 : (nzoff ? 0 : 1);
        }
        __syncthreads();
        int b = tid, m = mode, v;
        if (m == 0)      v = (dones_raw[b] != 0);
        else if (m == 1) v = (((const int*)dones_raw)[b] != 0);
        else             v = (((const float*)dones_raw)[b] != 0.0f);
        g_dones[b] = v;
    } else if (bid < 10) {
        int s = (bid - 1) * 256 + tid;
        if (s < SYNCHx) {
            float c = fminf(fmaxf(dp[s], 0.0f), 4.0f);
            float sum = 0.0f;
            for (int m = 0; m < Mx; m++) {
                float v = __expf(-(float)(Mx - 1 - m) * c);
                g_decay[m * SYNCHx + s] = v;
                sum += v;
            }
            g_invden[s] = rsqrtf(sum);
            int i = 0, base = 0;
            while (s >= base + (NSYx - i)) { base += NSYx - i; i++; }
            g_tri_i[s] = i;
            g_tri_j[s] = i + (s - base);
        }
    } else if (bid < 266) {
        int i = (bid - 10) * 256 + tid;
        split2(obs[i], &g_obshi[i], &g_obslo[i]);
    } else if (bid < 522) {
        tsplit_block(bw1, 256, 1024, g_wb1hi, g_wb1lo, bid - 266);
    } else {
        tsplit_block(bw2, 512, 1024, g_wb2hi, g_wb2lo, bid - 522);
    }
}

__global__ void __launch_bounds__(256) k_prep_side(
    const float* __restrict__ nw1, const float* __restrict__ nw2,
    const float* __restrict__ sw1, const float* __restrict__ sw2) {
    int bid = blockIdx.x, tid = threadIdx.x;
    if (bid < 4096) {
        int idx = bid * 256 + tid;
        int d = idx >> 10, hm = idx & 1023;
        int h = hm >> 5, m = hm & 31;
        float v = nw1[(m * 32 + h) * Dx + d];
        split2(v, &g_w1bh[idx], &g_w1bl[idx]);
        if (idx < Dx * 32) {
            int d2 = idx >> 5, hc = idx & 31;
            g_w2t[idx] = nw2[hc * Dx + d2];
        }
    } else if (bid < 7168) {
        tsplit_block(sw1, 1536, 2048, g_ws1hi, g_ws1lo, bid - 4096);
    } else {
        tsplit_block(sw2, 1024, 2048, g_ws2hi, g_ws2lo, bid - 7168);
    }
}

// ====== GLU + LN (sums KS split-K partials + bias) -> bf16 split ======
// KS compile-time -> unrolled independent loads. blockDim.x == halfN.
template<int KS>
__global__ void __launch_bounds__(1024) k_gluln_split(
    const float* __restrict__ y, int halfN,
    const float* __restrict__ bias,
    const float* __restrict__ sc, const float* __restrict__ bi,
    __nv_bfloat16* __restrict__ ohi, __nv_bfloat16* __restrict__ olo,
    int ostride, int gather,
    const float* __restrict__ at_in,
    const float* __restrict__ start_at) {
    __shared__ float red_s[32], red_q[32];
    int row = blockIdx.x, tid = threadIdx.x;
    int nw = blockDim.x >> 5;
    size_t rstride = (size_t)Bx * 2 * halfN;
    const float* yr = y + (size_t)row * 2 * halfN;
    int c = tid;
    float av[KS], gv[KS];
#pragma unroll
    for (int z = 0; z < KS; z++) {
        av[z] = yr[z * rstride + c];
        gv[z] = yr[z * rstride + halfN + c];
    }
    float a = bias[c];
    float g = bias[halfN + c];
#pragma unroll
    for (int z = 0; z < KS; z++) { a += av[z]; g += gv[z]; }
    float val = a * sigf(g);
    float sum = val, sq = val * val;
#pragma unroll
    for (int o = 16; o > 0; o >>= 1) {
        sum += __shfl_xor_sync(0xffffffffu, sum, o);
        sq  += __shfl_xor_sync(0xffffffffu, sq, o);
    }
    int w = tid >> 5;
    if ((tid & 31) == 0) { red_s[w] = sum; red_q[w] = sq; }
    __syncthreads();
    if (tid == 0) {
        float ts = 0.0f, tq = 0.0f;
        for (int i = 0; i < nw; i++) { ts += red_s[i]; tq += red_q[i]; }
        red_s[0] = ts; red_q[0] = tq;
    }
    __syncthreads();
    float invN = 1.0f / (float)halfN;
    float mean = red_s[0] * invN;
    float var = red_q[0] * invN - mean * mean;
    float inv = rsqrtf(var + 1e-6f);
    {
        float o_ = (val - mean) * inv * sc[c] + bi[c];
        size_t o = (size_t)row * ostride + c;
        split2(o_, &ohi[o], &olo[o]);
    }
    if (gather) {
        bool done = g_dones[row] != 0;
        for (int cc = tid; cc < Dx; cc += blockDim.x) {
            float v2 = done ? start_at[cc * 32 + 31]
                            : at_in[((size_t)(row * Dx + cc)) * 32 + 31];
            size_t o = (size_t)row * ostride + halfN + cc;
            split2(v2, &ohi[o], &olo[o]);
        }
    }
}

// GLU + LN -> fp32 contiguous (h_st[i]); blockDim==halfN; KS compile-time
template<int KS>
__global__ void __launch_bounds__(1024) k_gluln_f32(
    const float* __restrict__ y, int halfN,
    const float* __restrict__ bias,
    const float* __restrict__ sc, const float* __restrict__ bi,
    float* __restrict__ out) {
    __shared__ float red_s[32], red_q[32];
    int row = blockIdx.x, tid = threadIdx.x;
    int nw = blockDim.x >> 5;
    size_t rstride = (size_t)Bx * 2 * halfN;
    const float* yr = y + (size_t)row * 2 * halfN;
    int c = tid;
    float av[KS], gv[KS];
#pragma unroll
    for (int z = 0; z < KS; z++) {
        av[z] = yr[z * rstride + c];
        gv[z] = yr[z * rstride + halfN + c];
    }
    float a = bias[c];
    float g = bias[halfN + c];
#pragma unroll
    for (int z = 0; z < KS; z++) { a += av[z]; g += gv[z]; }
    float val = a * sigf(g);
    float sum = val, sq = val * val;
#pragma unroll
    for (int o = 16; o > 0; o >>= 1) {
        sum += __shfl_xor_sync(0xffffffffu, sum, o);
        sq  += __shfl_xor_sync(0xffffffffu, sq, o);
    }
    int w = tid >> 5;
    if ((tid & 31) == 0) { red_s[w] = sum; red_q[w] = sq; }
    __syncthreads();
    if (tid == 0) {
        float ts = 0.0f, tq = 0.0f;
        for (int i = 0; i < nw; i++) { ts += red_s[i]; tq += red_q[i]; }
        red_s[0] = ts; red_q[0] = tq;
    }
    __syncthreads();
    float invN = 1.0f / (float)halfN;
    float mean = red_s[0] * invN;
    float var = red_q[0] * invN - mean * mean;
    float inv = rsqrtf(var + 1e-6f);
    out[(size_t)row * halfN + c] = (val - mean) * inv * sc[c] + bi[c];
}

// ================= NLM via tensor cores (one d per block) =================
template<int IT>
__global__ void __launch_bounds__(256) k_nlm_tc(
    const float* __restrict__ st_in, const float* __restrict__ start_st,
    const float* __restrict__ b1, const float* __restrict__ T1,
    const float* __restrict__ b2, const float* __restrict__ T2) {
    __shared__ __align__(16) uint8_t Sh[16384], Sl[16384];
    __shared__ __align__(16) uint8_t Wh[2048], Wl[2048];
    __shared__ float w2s[32], b1s[32], b2s[2], invT[2];
    int tid = threadIdx.x;
    int lane = tid & 31;
    int w = tid >> 5;
    int d = blockIdx.x;

    if (tid < 128) {
        uint4 vh = ((const uint4*)(g_w1bh + (size_t)d * 1024))[tid];
        uint4 vl = ((const uint4*)(g_w1bl + (size_t)d * 1024))[tid];
        uint32_t off = (uint32_t)tid * 16;
        uint32_t so = SW64(off);
        *(uint4*)(Wh + so) = vh;
        *(uint4*)(Wl + so) = vl;
    }
    if (tid < 32) { w2s[tid] = g_w2t[d * 32 + tid]; b1s[tid] = b1[d * 32 + tid]; }
    if (tid < 2)  b2s[tid] = b2[d * 2 + tid];
    if (tid == 0) { invT[0] = 1.0f / T1[0]; invT[1] = 1.0f / T2[0]; }

    {
        int b = tid;
        const float* stp = g_dones[b] ? (start_st + d * 32)
                                      : (st_in + ((size_t)(b << 10) + d) * 32);
        float sar[32];
#pragma unroll
        for (int q = 0; q < 8; q++) {
            float4 t4 = ((const float4*)stp)[q];
            sar[q * 4 + 0] = t4.x; sar[q * 4 + 1] = t4.y;
            sar[q * 4 + 2] = t4.z; sar[q * 4 + 3] = t4.w;
        }
        float vals[32];
#pragma unroll
        for (int k = 0; k < 31 - IT; k++) vals[k] = sar[k + IT + 1];
#pragma unroll
        for (int j = 0; j <= IT; j++) vals[31 - IT + j] = g_hst[j][(size_t)b * 1024 + d];
#pragma unroll
        for (int q = 0; q < 4; q++) {
            uint32_t ph[4], pl[4];
#pragma unroll
            for (int p = 0; p < 4; p++)
                split_pack(vals[q * 8 + p * 2], vals[q * 8 + p * 2 + 1], ph[p], pl[p]);
            uint32_t off = (uint32_t)(b * 64 + q * 16);
            uint32_t so = SW64(off);
            *(uint4*)(Sh + so) = make_uint4(ph[0], ph[1], ph[2], ph[3]);
            *(uint4*)(Sl + so) = make_uint4(pl[0], pl[1], pl[2], pl[3]);
        }
    }
    __syncthreads();

    uint32_t sbh = smem_u32(Sh), sbl = smem_u32(Sl);
    uint32_t wbh = smem_u32(Wh), wbl = smem_u32(Wl);

    float acc[2][4][4];
#pragma unroll
    for (int mt = 0; mt < 2; mt++)
#pragma unroll
        for (int f = 0; f < 4; f++)
#pragma unroll
            for (int q = 0; q < 4; q++) acc[mt][f][q] = 0.0f;

#pragma unroll
    for (int ks = 0; ks < 2; ks++) {
        int cbA = ks * 32 + ((lane >> 4) << 4);
        uint32_t ah[2][4], al[2][4];
#pragma unroll
        for (int mt = 0; mt < 2; mt++) {
            int row = w * 32 + mt * 16 + (lane & 15);
            uint32_t off = SW64((uint32_t)(row * 64 + cbA));
            LDSM4(ah[mt], sbh + off);
            LDSM4(al[mt], sbl + off);
        }
        uint32_t bh[8], bl[8];
        int cbB = ks * 32 + (((lane >> 3) & 1) << 4);
#pragma unroll
        for (int g = 0; g < 2; g++) {
            int rowb = g * 16 + (lane & 7) + ((lane >> 4) << 3);
            uint32_t off = SW64((uint32_t)(rowb * 64 + cbB));
            LDSM4(bh + g * 4, wbh + off);
            LDSM4(bl + g * 4, wbl + off);
        }
#pragma unroll
        for (int mt = 0; mt < 2; mt++) {
#pragma unroll
            for (int f = 0; f < 4; f++) {
                MMA16816(acc[mt][f], ah[mt], bh[2 * f], bh[2 * f + 1]);
                MMA16816(acc[mt][f], ah[mt], bl[2 * f], bl[2 * f + 1]);
                MMA16816(acc[mt][f], al[mt], bh[2 * f], bh[2 * f + 1]);
            }
        }
    }

    int gid = lane >> 2, tig = lane & 3;
    float iT1 = invT[0], iT2 = invT[1];
#pragma unroll
    for (int mt = 0; mt < 2; mt++) {
#pragma unroll
        for (int rsel = 0; rsel < 2; rsel++) {
            float y0 = 0.0f, y1 = 0.0f;
#pragma unroll
            for (int f = 0; f < 2; f++) {
#pragma unroll
                for (int c2 = 0; c2 < 2; c2++) {
                    int h = f * 8 + tig * 2 + c2;
                    float xv = acc[mt][f][rsel * 2 + c2] + b1s[h];
                    float gv = acc[mt][f + 2][rsel * 2 + c2] + b1s[h + 16];
                    float u = (xv * iT1) * sigf(gv * iT1);
                    y0 += u * w2s[h * 2 + 0];
                    y1 += u * w2s[h * 2 + 1];
                }
            }
            y0 += __shfl_xor_sync(0xffffffffu, y0, 1);
            y0 += __shfl_xor_sync(0xffffffffu, y0, 2);
            y1 += __shfl_xor_sync(0xffffffffu, y1, 1);
            y1 += __shfl_xor_sync(0xffffffffu, y1, 2);
            if (tig == 0) {
                float fy0 = y0 + b2s[0];
                float fy1 = y1 + b2s[1];
                float r = (fy0 * iT2) * sigf(fy1 * iT2);
                int brow = w * 32 + mt * 16 + rsel * 8 + gid;
                g_hat[IT][(size_t)d * Bx + brow] = r;
                if (IT < 3) {
                    __nv_bfloat16 hh, ll;
                    split2(r, &hh, &ll);
                    size_t o = (size_t)brow * (DINx + Dx) + DINx + d;
                    g_prehi[o] = hh; g_prelo[o] = ll;
                }
            }
        }
    }
}

// ================= final assembly + synchrony =================
__global__ void __launch_bounds__(256) k_fin(
    float* __restrict__ out,
    const float* __restrict__ st_in, const float* __restrict__ at_in,
    const float* __restrict__ start_st, const float* __restrict__ start_at) {
    int tid = threadIdx.x;
    if (blockIdx.x < 1024) {
        __shared__ float hsm[4][32][9];
        int local = blockIdx.x;
        int dt = local & 127, bt = local >> 7;
        int d0 = dt * 8, b0 = bt * 32;
        {
            int j = tid >> 6, rem = tid & 63, bl = rem >> 1, hf = rem & 1;
            float4 hv = *(const float4*)&g_hst[j][(size_t)(b0 + bl) * Dx + d0 + hf * 4];
            hsm[j][bl][hf * 4 + 0] = hv.x;
            hsm[j][bl][hf * 4 + 1] = hv.y;
            hsm[j][bl][hf * 4 + 2] = hv.z;
            hsm[j][bl][hf * 4 + 3] = hv.w;
        }
        __syncthreads();
        int w = tid >> 5, lane = tid & 31;
        int d = d0 + w, b = b0 + lane;
        bool done = g_dones[b] != 0;
        const float* stp = done ? (start_st + d * 32) : (st_in + ((size_t)(b << 10) + d) * 32);
        const float* atp = done ? (start_at + d * 32) : (at_in + ((size_t)(b << 10) + d) * 32);
        float so[32], ao[32];
#pragma unroll
        for (int q = 1; q < 8; q++) {
            float4 t4 = ((const float4*)stp)[q];
            so[q * 4 - 4] = t4.x; so[q * 4 - 3] = t4.y; so[q * 4 - 2] = t4.z; so[q * 4 - 1] = t4.w;
            float4 u4 = ((const float4*)atp)[q];
            ao[q * 4 - 4] = u4.x; ao[q * 4 - 3] = u4.y; ao[q * 4 - 2] = u4.z; ao[q * 4 - 1] = u4.w;
        }
#pragma unroll
        for (int j = 0; j < 4; j++) {
            so[28 + j] = hsm[j][lane][w];
            ao[28 + j] = g_hat[j][(size_t)d * Bx + b];
        }
        float* o1 = out + ((size_t)(b << 10) + d) * 32;
        float* o2 = o1 + BDMx;
#pragma unroll
        for (int q = 0; q < 8; q++) {
            float4 v1 = { so[q * 4], so[q * 4 + 1], so[q * 4 + 2], so[q * 4 + 3] };
            float4 v2 = { ao[q * 4], ao[q * 4 + 1], ao[q * 4 + 2], ao[q * 4 + 3] };
            ((float4*)o1)[q] = v1;
            ((float4*)o2)[q] = v2;
        }
    } else {
        __shared__ float S[Mx * NSYx];
        int b = blockIdx.x - 1024;
        bool done = g_dones[b] != 0;
        float* outs = out + 2 * (size_t)BDMx;
        for (int t = tid; t < Mx * NSYx; t += 256) {
            int m = t & 31, j = t >> 5;
            int dd = Dx - NSYx + j;
            float val;
            if (m < 28)
                val = done ? start_at[dd * 32 + m + 4]
                           : at_in[((size_t)(b * Dx + dd)) * 32 + m + 4];
            else
                val = g_hat[m - 28][(size_t)dd * Bx + b];
            S[m * NSYx + j] = val;
        }
        __syncthreads();
        for (int s = tid; s < SYNCHx; s += 256) {
            int ti = g_tri_i[s], tj = g_tri_j[s];
            float acc = 0.0f;
#pragma unroll
            for (int m = 0; m < Mx; m++)
                acc += g_decay[m * SYNCHx + s] * S[m * NSYx + ti] * S[m * NSYx + tj];
            outs[(size_t)b * SYNCHx + s] = acc * g_invden[s];
        }
    }
}

// =====================================================================
extern "C" void kernel_launch(void* const* d_in, const int* in_sizes, int n_in,
                              void* d_out, int out_size) {
    (void)in_sizes; (void)n_in; (void)out_size;
    const float* obs      = (const float*)d_in[0];
    const unsigned char* dones_raw = (const unsigned char*)d_in[1];
    const float* st_in    = (const float*)d_in[3];
    const float* at_in    = (const float*)d_in[4];
    const float* start_st = (const float*)d_in[5];
    const float* start_at = (const float*)d_in[6];
    const float* bb_w1    = (const float*)d_in[7];
    const float* bb_b1    = (const float*)d_in[8];
    const float* ln1s     = (const float*)d_in[9];
    const float* ln1b     = (const float*)d_in[10];
    const float* bb_w2    = (const float*)d_in[11];
    const float* bb_b2    = (const float*)d_in[12];
    const float* ln2s     = (const float*)d_in[13];
    const float* ln2b     = (const float*)d_in[14];
    const float* syn_w1   = (const float*)d_in[15];
    const float* syn_b1   = (const float*)d_in[16];
    const float* sln1s    = (const float*)d_in[17];
    const float* sln1b    = (const float*)d_in[18];
    const float* syn_w2   = (const float*)d_in[19];
    const float* syn_b2   = (const float*)d_in[20];
    const float* sln2s    = (const float*)d_in[21];
    const float* sln2b    = (const float*)d_in[22];
    const float* nlm1_w   = (const float*)d_in[23];
    const float* nlm1_b   = (const float*)d_in[24];
    const float* nlm1_T   = (const float*)d_in[25];
    const float* nlm2_w   = (const float*)d_in[26];
    const float* nlm2_b   = (const float*)d_in[27];
    const float* nlm2_T   = (const float*)d_in[28];
    const float* decay_p  = (const float*)d_in[29];
    float* out = (float*)d_out;

    void *p_y, *p_hst;
    void *p_obshi, *p_obslo, *p_prehi, *p_prelo, *p_h1hi, *p_h1lo;
    void *p_wb1h, *p_wb1l, *p_wb2h, *p_wb2l, *p_ws1h, *p_ws1l, *p_ws2h, *p_ws2l;
    cudaGetSymbolAddress(&p_y, g_y);
    cudaGetSymbolAddress(&p_hst, g_hst);
    cudaGetSymbolAddress(&p_obshi, g_obshi);  cudaGetSymbolAddress(&p_obslo, g_obslo);
    cudaGetSymbolAddress(&p_prehi, g_prehi);  cudaGetSymbolAddress(&p_prelo, g_prelo);
    cudaGetSymbolAddress(&p_h1hi, g_h1hi);    cudaGetSymbolAddress(&p_h1lo, g_h1lo);
    cudaGetSymbolAddress(&p_wb1h, g_wb1hi);   cudaGetSymbolAddress(&p_wb1l, g_wb1lo);
    cudaGetSymbolAddress(&p_wb2h, g_wb2hi);   cudaGetSymbolAddress(&p_wb2l, g_wb2lo);
    cudaGetSymbolAddress(&p_ws1h, g_ws1hi);   cudaGetSymbolAddress(&p_ws1l, g_ws1lo);
    cudaGetSymbolAddress(&p_ws2h, g_ws2hi);   cudaGetSymbolAddress(&p_ws2l, g_ws2lo);
    float* gy   = (float*)p_y;
    float* ghst = (float*)p_hst;

    static int init_done = 0;
    static cudaStream_t s_side = nullptr;
    static cudaEvent_t ev_fork = nullptr, ev_join = nullptr;
    int gsmem = GSTAGES * GBUF_BYTES + 1024;
    if (!init_done) {
        cudaFuncSetAttribute(k_tgemm, cudaFuncAttributeMaxDynamicSharedMemorySize, gsmem);
        cudaStreamCreateWithFlags(&s_side, cudaStreamNonBlocking);
        cudaEventCreateWithFlags(&ev_fork, cudaEventDisableTiming);
        cudaEventCreateWithFlags(&ev_join, cudaEventDisableTiming);
        init_done = 1;
    }

    // fork: side branch preps NLM + synapse weights
    cudaEventRecord(ev_fork, 0);
    cudaStreamWaitEvent(s_side, ev_fork, 0);
    k_prep_side<<<9216, 256, 0, s_side>>>(nlm1_w, nlm2_w, syn_w1, syn_w2);
    cudaEventRecord(ev_join, s_side);

    // main branch: light prep + backbone
    k_prep_main<<<1034, 256>>>(dones_raw, decay_p, obs, bb_w1, bb_w2);

    k_tgemm<<<dim3(16, 4, 2), 256, gsmem>>>(
        (const __nv_bfloat16*)p_obshi, (const __nv_bfloat16*)p_obslo,
        (const __nv_bfloat16*)p_wb1h, (const __nv_bfloat16*)p_wb1l,
        gy, 0, 128, 256, 256, 1024);
    k_gluln_split<2><<<Bx, 512>>>(gy, 512, bb_b1, ln1s, ln1b,
        (__nv_bfloat16*)p_h1hi, (__nv_bfloat16*)p_h1lo, 512, 0, nullptr, nullptr);
    k_tgemm<<<dim3(16, 4, 2), 256, gsmem>>>(
        (const __nv_bfloat16*)p_h1hi, (const __nv_bfloat16*)p_h1lo,
        (const __nv_bfloat16*)p_wb2h, (const __nv_bfloat16*)p_wb2l,
        gy, 0, 256, 512, 512, 1024);
    k_gluln_split<2><<<Bx, 512>>>(gy, 512, bb_b2, ln2s, ln2b,
        (__nv_bfloat16*)p_prehi, (__nv_bfloat16*)p_prelo, 1536, 1, at_in, start_at);

    // join: synapse + NLM weights ready
    cudaStreamWaitEvent(0, ev_join, 0);

    // hoisted f-part of synapse GEMM1 (iteration-invariant): K=0..512 -> slice 2
    k_tgemm<<<dim3(32, 4, 1), 256, gsmem>>>(
        (const __nv_bfloat16*)p_prehi, (const __nv_bfloat16*)p_prelo,
        (const __nv_bfloat16*)p_ws1h, (const __nv_bfloat16*)p_ws1l,
        gy + 2 * (size_t)Bx * 2048, 0, 512, 1536, 1536, 2048);

    for (int i = 0; i < ITERSx; i++) {
        // synapse GEMM1, at-part only: K=512..1536, KS=2
        k_tgemm<<<dim3(32, 4, 2), 256, gsmem>>>(
            (const __nv_bfloat16*)p_prehi, (const __nv_bfloat16*)p_prelo,
            (const __nv_bfloat16*)p_ws1h, (const __nv_bfloat16*)p_ws1l,
            gy, 512, 512, 1536, 1536, 2048);
        k_gluln_split<3><<<Bx, 1024>>>(gy, 1024, syn_b1, sln1s, sln1b,
            (__nv_bfloat16*)p_h1hi, (__nv_bfloat16*)p_h1lo, 1024, 0, nullptr, nullptr);
        // synapse GEMM2 K=1024, KS=2
        k_tgemm<<<dim3(32, 4, 2), 256, gsmem>>>(
            (const __nv_bfloat16*)p_h1hi, (const __nv_bfloat16*)p_h1lo,
            (const __nv_bfloat16*)p_ws2h, (const __nv_bfloat16*)p_ws2l,
            gy, 0, 512, 1024, 1024, 2048);
        k_gluln_f32<2><<<Bx, 1024>>>(gy, 1024, syn_b2, sln2s, sln2b,
            ghst + (size_t)i * BDx);
        switch (i) {
            case 0: k_nlm_tc<0><<<1024, 256>>>(st_in, start_st, nlm1_b, nlm1_T, nlm2_b, nlm2_T); break;
            case 1: k_nlm_tc<1><<<1024, 256>>>(st_in, start_st, nlm1_b, nlm1_T, nlm2_b, nlm2_T); break;
            case 2: k_nlm_tc<2><<<1024, 256>>>(st_in, start_st, nlm1_b, nlm1_T, nlm2_b, nlm2_T); break;
            case 3: k_nlm_tc<3><<<1024, 256>>>(st_in, start_st, nlm1_b, nlm1_T, nlm2_b, nlm2_T); break;
        }
    }

    k_fin<<<1024 + Bx, 256>>>(out, st_in, at_in, start_st, start_at);
}

// round 15
// speedup vs baseline: 1.4245x; 1.0140x over previous
#include <cuda_runtime.h>
#include <cuda_bf16.h>
#include <math.h>
#include <stdint.h>

#define Bx    256
#define OBSx  256
#define DINx  512
#define Dx    1024
#define Mx    32
#define HIDx  16
#define NSYx  64
#define ITERSx 4
#define SYNCHx 2080
#define BDx   (Bx * Dx)          // 262144
#define BDMx  (Bx * Dx * Mx)     // 8388608

// ---------------- scratch (static device globals) ----------------
__device__ float g_y[4 * Bx * 2 * Dx];               // split-K partial slices
__device__ __align__(16) __nv_bfloat16 g_w1bh[Dx * 1024];  // [d][h*32+m] bf16 hi
__device__ __align__(16) __nv_bfloat16 g_w1bl[Dx * 1024];  // [d][h*32+m] bf16 lo
__device__ float g_w2t[Dx * 32];
__device__ float g_decay[Mx * SYNCHx];
__device__ float g_invden[SYNCHx];
__device__ int   g_tri_i[SYNCHx];
__device__ int   g_tri_j[SYNCHx];
__device__ int   g_dones[Bx];
__device__ __align__(16) float g_hst[ITERSx][BDx];   // [i][b*1024+d]
__device__ __align__(16) float g_hat[ITERSx][BDx];   // [i][d*256+b]

__device__ __align__(256) __nv_bfloat16 g_obshi[Bx * OBSx];
__device__ __align__(256) __nv_bfloat16 g_obslo[Bx * OBSx];
__device__ __align__(256) __nv_bfloat16 g_prehi[Bx * (DINx + Dx)];
__device__ __align__(256) __nv_bfloat16 g_prelo[Bx * (DINx + Dx)];
__device__ __align__(256) __nv_bfloat16 g_h1hi[Bx * Dx];
__device__ __align__(256) __nv_bfloat16 g_h1lo[Bx * Dx];
__device__ __align__(256) __nv_bfloat16 g_wb1hi[1024 * 256];
__device__ __align__(256) __nv_bfloat16 g_wb1lo[1024 * 256];
__device__ __align__(256) __nv_bfloat16 g_wb2hi[1024 * 512];
__device__ __align__(256) __nv_bfloat16 g_wb2lo[1024 * 512];
__device__ __align__(256) __nv_bfloat16 g_ws1hi[2048 * 1536];
__device__ __align__(256) __nv_bfloat16 g_ws1lo[2048 * 1536];
__device__ __align__(256) __nv_bfloat16 g_ws2hi[2048 * 1024];
__device__ __align__(256) __nv_bfloat16 g_ws2lo[2048 * 1024];

__device__ __forceinline__ float sigf(float x) {
    return __fdividef(1.0f, 1.0f + __expf(-x));
}
__device__ __forceinline__ void split2(float v, __nv_bfloat16* h, __nv_bfloat16* l) {
    __nv_bfloat16 hh = __float2bfloat16(v);
    *h = hh;
    *l = __float2bfloat16(v - __bfloat162float(hh));
}
__device__ __forceinline__ void split_pack(float v0, float v1, uint32_t& ph, uint32_t& pl) {
    __nv_bfloat16 h0 = __float2bfloat16(v0);
    __nv_bfloat16 h1 = __float2bfloat16(v1);
    __nv_bfloat16 l0 = __float2bfloat16(v0 - __bfloat162float(h0));
    __nv_bfloat16 l1 = __float2bfloat16(v1 - __bfloat162float(h1));
    unsigned short u0, u1;
    memcpy(&u0, &h0, 2); memcpy(&u1, &h1, 2);
    ph = (uint32_t)u0 | ((uint32_t)u1 << 16);
    memcpy(&u0, &l0, 2); memcpy(&u1, &l1, 2);
    pl = (uint32_t)u0 | ((uint32_t)u1 << 16);
}

// ================= PTX helpers =================
__device__ __forceinline__ uint32_t smem_u32(const void* p) {
    uint32_t a;
    asm("{ .reg .u64 t; cvta.to.shared.u64 t, %1; cvt.u32.u64 %0, t; }" : "=r"(a) : "l"(p));
    return a;
}
#define SW128(off) ((off) ^ (((off) >> 3) & 0x70))
#define SW64(off)  ((off) ^ (((off) >> 3) & 0x30))
#define CP_ASYNC16(dst, src) \
    asm volatile("cp.async.cg.shared.global [%0], [%1], 16;" :: "r"(dst), "l"(src))
#define CP_COMMIT()  asm volatile("cp.async.commit_group;" ::: "memory")
#define CP_WAIT(n)   asm volatile("cp.async.wait_group %0;" :: "n"(n) : "memory")
#define LDSM4(r, addr) \
    asm volatile("ldmatrix.sync.aligned.m8n8.x4.shared.b16 {%0,%1,%2,%3}, [%4];" \
        : "=r"((r)[0]), "=r"((r)[1]), "=r"((r)[2]), "=r"((r)[3]) : "r"(addr))
#define MMA16816(acc, a, b0, b1) \
    asm volatile("mma.sync.aligned.m16n8k16.row.col.f32.bf16.bf16.f32 " \
        "{%0,%1,%2,%3}, {%4,%5,%6,%7}, {%8,%9}, {%0,%1,%2,%3};" \
        : "+f"((acc)[0]), "+f"((acc)[1]), "+f"((acc)[2]), "+f"((acc)[3]) \
        : "r"((a)[0]), "r"((a)[1]), "r"((a)[2]), "r"((a)[3]), "r"(b0), "r"(b1))

// ================= split-bf16 HMMA GEMM, split-K with K-base offset =========
#define GBUF_BYTES 32768
#define GSTAGES 3
__global__ void __launch_bounds__(256) k_tgemm(
    const __nv_bfloat16* __restrict__ Ahi, const __nv_bfloat16* __restrict__ Alo,
    const __nv_bfloat16* __restrict__ Bhi, const __nv_bfloat16* __restrict__ Blo,
    float* __restrict__ C, int kbase, int Kloc, int lda, int ldb, int N)
{
    extern __shared__ char smem_raw[];
    uint32_t sbase = smem_u32(smem_raw);
    uint32_t abase = (sbase + 1023u) & ~1023u;

    int tid = threadIdx.x;
    int lane = tid & 31;
    int wid = tid >> 5;
    int warp_m = wid & 1;
    int warp_n = wid >> 1;
    int row0 = blockIdx.y * 64;
    int col0 = blockIdx.x * 64;
    int koff = kbase + blockIdx.z * Kloc;
    int NC = Kloc >> 6;

    float acc[2][2][4];
#pragma unroll
    for (int i = 0; i < 2; i++)
#pragma unroll
        for (int j = 0; j < 2; j++)
#pragma unroll
            for (int q = 0; q < 4; q++) acc[i][j][q] = 0.0f;

    auto load_chunk = [&](int buf, int k0) {
        uint32_t bb = abase + buf * GBUF_BYTES;
#pragma unroll
        for (int i = 0; i < 2; i++) {
            int u = tid + i * 256;
            int r = u >> 3, ch = u & 7;
            uint32_t soff = SW128((uint32_t)(r * 128 + ch * 16));
            size_t goA = (size_t)(row0 + r) * lda + koff + k0 + ch * 8;
            size_t goB = (size_t)(col0 + r) * ldb + koff + k0 + ch * 8;
            CP_ASYNC16(bb + soff,          Ahi + goA);
            CP_ASYNC16(bb + 8192 + soff,   Alo + goA);
            CP_ASYNC16(bb + 16384 + soff,  Bhi + goB);
            CP_ASYNC16(bb + 24576 + soff,  Blo + goB);
        }
    };

    load_chunk(0, 0);
    CP_COMMIT();
    load_chunk(1, 64);
    CP_COMMIT();

    int a_r = warp_m * 32 + (lane & 15);
    int a_csel = (lane >> 4) << 3;
    int b_r = warp_n * 16 + (lane & 7) + ((lane >> 4) << 3);
    int b_csel = ((lane >> 3) & 1) << 3;

    int buf = 0, pbuf = 2;
    for (int c = 0; c < NC; c++) {
        CP_WAIT(GSTAGES - 2);
        __syncthreads();
        if (c + 2 < NC) load_chunk(pbuf, (c + 2) * 64);
        CP_COMMIT();

        uint32_t bb = abase + buf * GBUF_BYTES;
#pragma unroll
        for (int kk = 0; kk < 4; kk++) {
            int k0 = kk * 16;
            uint32_t ah[2][4], al[2][4], bh[4], bl[4];
#pragma unroll
            for (int mf = 0; mf < 2; mf++) {
                uint32_t off = SW128((uint32_t)((a_r + mf * 16) * 128 + (k0 + a_csel) * 2));
                LDSM4(ah[mf], bb + off);
                LDSM4(al[mf], bb + 8192 + off);
            }
            {
                uint32_t off = SW128((uint32_t)(b_r * 128 + (k0 + b_csel) * 2));
                LDSM4(bh, bb + 16384 + off);
                LDSM4(bl, bb + 24576 + off);
            }
#pragma unroll
            for (int mf = 0; mf < 2; mf++) {
#pragma unroll
                for (int nf = 0; nf < 2; nf++) {
                    MMA16816(acc[mf][nf], ah[mf], bh[2 * nf], bh[2 * nf + 1]);
                    MMA16816(acc[mf][nf], ah[mf], bl[2 * nf], bl[2 * nf + 1]);
                    MMA16816(acc[mf][nf], al[mf], bh[2 * nf], bh[2 * nf + 1]);
                }
            }
        }
        buf = (buf == GSTAGES - 1) ? 0 : buf + 1;
        pbuf = (pbuf == GSTAGES - 1) ? 0 : pbuf + 1;
    }

    float* Cz = C + (size_t)blockIdx.z * Bx * N;
    int gid = lane >> 2, tig = lane & 3;
#pragma unroll
    for (int mf = 0; mf < 2; mf++) {
#pragma unroll
        for (int nf = 0; nf < 2; nf++) {
            int r = row0 + warp_m * 32 + mf * 16 + gid;
            int cc = col0 + warp_n * 16 + nf * 8 + tig * 2;
            float2 o0 = { acc[mf][nf][0], acc[mf][nf][1] };
            float2 o1 = { acc[mf][nf][2], acc[mf][nf][3] };
            *(float2*)&Cz[(size_t)r * N + cc] = o0;
            *(float2*)&Cz[(size_t)(r + 8) * N + cc] = o1;
        }
    }
}

// ================= prep kernels (main + side branch) =================
__device__ void tsplit_block(const float* __restrict__ W, int K, int N,
                             __nv_bfloat16* __restrict__ Ohi, __nv_bfloat16* __restrict__ Olo,
                             int local) {
    __shared__ float t[32][33];
    int ktiles = K >> 5;
    int kt = local % ktiles, nt = local / ktiles;
    int k0 = kt * 32, n0 = nt * 32;
    int tx = threadIdx.x & 31, ty = threadIdx.x >> 5;
    for (int i = ty; i < 32; i += 8)
        t[i][tx] = W[(size_t)(k0 + i) * N + n0 + tx];
    __syncthreads();
    for (int i = ty; i < 32; i += 8) {
        float v = t[tx][i];
        size_t o = (size_t)(n0 + i) * K + k0 + tx;
        __nv_bfloat16 h, l;
        split2(v, &h, &l);
        Ohi[o] = h; Olo[o] = l;
    }
}

__global__ void __launch_bounds__(256) k_prep_main(
    const unsigned char* __restrict__ dones_raw,
    const float* __restrict__ dp,
    const float* __restrict__ obs,
    const float* __restrict__ bw1, const float* __restrict__ bw2) {
    int bid = blockIdx.x, tid = threadIdx.x;
    if (bid == 0) {
        __shared__ int mode;
        if (tid == 0) {
            bool nzoff = false, floatlike = true, anynz = false;
            for (int i = 0; i < Bx; i++) {
                unsigned char v = dones_raw[i];
                if (v) {
                    anynz = true;
                    int r = i & 3;
                    if (r != 0) nzoff = true;
                    bool okf = (r == 2 && v == 0x80) || (r == 3 && v == 0x3F);
                    if (!okf) floatlike = false;
                }
            }
            mode = (nzoff && floatlike && anynz) ? 2 : (nzoff ? 0 : 1);
        }
        __syncthreads();
        int b = tid, m = mode, v;
        if (m == 0)      v = (dones_raw[b] != 0);
        else if (m == 1) v = (((const int*)dones_raw)[b] != 0);
        else             v = (((const float*)dones_raw)[b] != 0.0f);
        g_dones[b] = v;
    } else if (bid < 10) {
        int s = (bid - 1) * 256 + tid;
        if (s < SYNCHx) {
            float c = fminf(fmaxf(dp[s], 0.0f), 4.0f);
            float sum = 0.0f;
            for (int m = 0; m < Mx; m++) {
                float v = __expf(-(float)(Mx - 1 - m) * c);
                g_decay[m * SYNCHx + s] = v;
                sum += v;
            }
            g_invden[s] = rsqrtf(sum);
            int i = 0, base = 0;
            while (s >= base + (NSYx - i)) { base += NSYx - i; i++; }
            g_tri_i[s] = i;
            g_tri_j[s] = i + (s - base);
        }
    } else if (bid < 266) {
        int i = (bid - 10) * 256 + tid;
        split2(obs[i], &g_obshi[i], &g_obslo[i]);
    } else if (bid < 522) {
        tsplit_block(bw1, 256, 1024, g_wb1hi, g_wb1lo, bid - 266);
    } else {
        tsplit_block(bw2, 512, 1024, g_wb2hi, g_wb2lo, bid - 522);
    }
}

__global__ void __launch_bounds__(256) k_prep_side(
    const float* __restrict__ nw1, const float* __restrict__ nw2,
    const float* __restrict__ sw1, const float* __restrict__ sw2) {
    int bid = blockIdx.x, tid = threadIdx.x;
    if (bid < 4096) {
        int idx = bid * 256 + tid;
        int d = idx >> 10, hm = idx & 1023;
        int h = hm >> 5, m = hm & 31;
        float v = nw1[(m * 32 + h) * Dx + d];
        split2(v, &g_w1bh[idx], &g_w1bl[idx]);
        if (idx < Dx * 32) {
            int d2 = idx >> 5, hc = idx & 31;
            g_w2t[idx] = nw2[hc * Dx + d2];
        }
    } else if (bid < 7168) {
        tsplit_block(sw1, 1536, 2048, g_ws1hi, g_ws1lo, bid - 4096);
    } else {
        tsplit_block(sw2, 1024, 2048, g_ws2hi, g_ws2lo, bid - 7168);
    }
}

// ====== GLU + LN (sums KS split-K partials + bias) -> bf16 split ======
// KS compile-time -> unrolled independent loads. blockDim.x == halfN.
template<int KS>
__global__ void __launch_bounds__(1024) k_gluln_split(
    const float* __restrict__ y, int halfN,
    const float* __restrict__ bias,
    const float* __restrict__ sc, const float* __restrict__ bi,
    __nv_bfloat16* __restrict__ ohi, __nv_bfloat16* __restrict__ olo,
    int ostride, int gather,
    const float* __restrict__ at_in,
    const float* __restrict__ start_at) {
    __shared__ float red_s[32], red_q[32];
    int row = blockIdx.x, tid = threadIdx.x;
    int nw = blockDim.x >> 5;
    size_t rstride = (size_t)Bx * 2 * halfN;
    const float* yr = y + (size_t)row * 2 * halfN;
    int c = tid;
    float av[KS], gv[KS];
#pragma unroll
    for (int z = 0; z < KS; z++) {
        av[z] = yr[z * rstride + c];
        gv[z] = yr[z * rstride + halfN + c];
    }
    float a = bias[c];
    float g = bias[halfN + c];
#pragma unroll
    for (int z = 0; z < KS; z++) { a += av[z]; g += gv[z]; }
    float val = a * sigf(g);

    // independent gather: overlap with reduction latency
    if (gather) {
        bool done = g_dones[row] != 0;
        for (int cc = tid; cc < Dx; cc += blockDim.x) {
            float v2 = done ? start_at[cc * 32 + 31]
                            : at_in[((size_t)(row * Dx + cc)) * 32 + 31];
            size_t o = (size_t)row * ostride + halfN + cc;
            split2(v2, &ohi[o], &olo[o]);
        }
    }

    float sum = val, sq = val * val;
#pragma unroll
    for (int o = 16; o > 0; o >>= 1) {
        sum += __shfl_xor_sync(0xffffffffu, sum, o);
        sq  += __shfl_xor_sync(0xffffffffu, sq, o);
    }
    int w = tid >> 5;
    int lane = tid & 31;
    if (lane == 0) { red_s[w] = sum; red_q[w] = sq; }
    __syncthreads();
    if (w == 0) {
        float ts = (lane < nw) ? red_s[lane] : 0.0f;
        float tq = (lane < nw) ? red_q[lane] : 0.0f;
#pragma unroll
        for (int o = 16; o > 0; o >>= 1) {
            ts += __shfl_xor_sync(0xffffffffu, ts, o);
            tq += __shfl_xor_sync(0xffffffffu, tq, o);
        }
        if (lane == 0) { red_s[0] = ts; red_q[0] = tq; }
    }
    __syncthreads();
    float invN = 1.0f / (float)halfN;
    float mean = red_s[0] * invN;
    float var = red_q[0] * invN - mean * mean;
    float inv = rsqrtf(var + 1e-6f);
    {
        float o_ = (val - mean) * inv * sc[c] + bi[c];
        size_t o = (size_t)row * ostride + c;
        split2(o_, &ohi[o], &olo[o]);
    }
}

// GLU + LN -> fp32 contiguous (h_st[i]); blockDim==halfN; KS compile-time
template<int KS>
__global__ void __launch_bounds__(1024) k_gluln_f32(
    const float* __restrict__ y, int halfN,
    const float* __restrict__ bias,
    const float* __restrict__ sc, const float* __restrict__ bi,
    float* __restrict__ out) {
    __shared__ float red_s[32], red_q[32];
    int row = blockIdx.x, tid = threadIdx.x;
    int nw = blockDim.x >> 5;
    size_t rstride = (size_t)Bx * 2 * halfN;
    const float* yr = y + (size_t)row * 2 * halfN;
    int c = tid;
    float av[KS], gv[KS];
#pragma unroll
    for (int z = 0; z < KS; z++) {
        av[z] = yr[z * rstride + c];
        gv[z] = yr[z * rstride + halfN + c];
    }
    float a = bias[c];
    float g = bias[halfN + c];
#pragma unroll
    for (int z = 0; z < KS; z++) { a += av[z]; g += gv[z]; }
    float val = a * sigf(g);
    float sum = val, sq = val * val;
#pragma unroll
    for (int o = 16; o > 0; o >>= 1) {
        sum += __shfl_xor_sync(0xffffffffu, sum, o);
        sq  += __shfl_xor_sync(0xffffffffu, sq, o);
    }
    int w = tid >> 5;
    int lane = tid & 31;
    if (lane == 0) { red_s[w] = sum; red_q[w] = sq; }
    __syncthreads();
    if (w == 0) {
        float ts = (lane < nw) ? red_s[lane] : 0.0f;
        float tq = (lane < nw) ? red_q[lane] : 0.0f;
#pragma unroll
        for (int o = 16; o > 0; o >>= 1) {
            ts += __shfl_xor_sync(0xffffffffu, ts, o);
            tq += __shfl_xor_sync(0xffffffffu, tq, o);
        }
        if (lane == 0) { red_s[0] = ts; red_q[0] = tq; }
    }
    __syncthreads();
    float invN = 1.0f / (float)halfN;
    float mean = red_s[0] * invN;
    float var = red_q[0] * invN - mean * mean;
    float inv = rsqrtf(var + 1e-6f);
    out[(size_t)row * halfN + c] = (val - mean) * inv * sc[c] + bi[c];
}

// ================= NLM via tensor cores (one d per block) =================
template<int IT>
__global__ void __launch_bounds__(256) k_nlm_tc(
    const float* __restrict__ st_in, const float* __restrict__ start_st,
    const float* __restrict__ b1, const float* __restrict__ T1,
    const float* __restrict__ b2, const float* __restrict__ T2) {
    __shared__ __align__(16) uint8_t Sh[16384], Sl[16384];
    __shared__ __align__(16) uint8_t Wh[2048], Wl[2048];
    __shared__ float w2s[32], b1s[32], b2s[2], invT[2];
    int tid = threadIdx.x;
    int lane = tid & 31;
    int w = tid >> 5;
    int d = blockIdx.x;

    if (tid < 128) {
        uint4 vh = ((const uint4*)(g_w1bh + (size_t)d * 1024))[tid];
        uint4 vl = ((const uint4*)(g_w1bl + (size_t)d * 1024))[tid];
        uint32_t off = (uint32_t)tid * 16;
        uint32_t so = SW64(off);
        *(uint4*)(Wh + so) = vh;
        *(uint4*)(Wl + so) = vl;
    }
    if (tid < 32) { w2s[tid] = g_w2t[d * 32 + tid]; b1s[tid] = b1[d * 32 + tid]; }
    if (tid < 2)  b2s[tid] = b2[d * 2 + tid];
    if (tid == 0) { invT[0] = 1.0f / T1[0]; invT[1] = 1.0f / T2[0]; }

    {
        int b = tid;
        const float* stp = g_dones[b] ? (start_st + d * 32)
                                      : (st_in + ((size_t)(b << 10) + d) * 32);
        float sar[32];
#pragma unroll
        for (int q = 0; q < 8; q++) {
            float4 t4 = ((const float4*)stp)[q];
            sar[q * 4 + 0] = t4.x; sar[q * 4 + 1] = t4.y;
            sar[q * 4 + 2] = t4.z; sar[q * 4 + 3] = t4.w;
        }
        float vals[32];
#pragma unroll
        for (int k = 0; k < 31 - IT; k++) vals[k] = sar[k + IT + 1];
#pragma unroll
        for (int j = 0; j <= IT; j++) vals[31 - IT + j] = g_hst[j][(size_t)b * 1024 + d];
#pragma unroll
        for (int q = 0; q < 4; q++) {
            uint32_t ph[4], pl[4];
#pragma unroll
            for (int p = 0; p < 4; p++)
                split_pack(vals[q * 8 + p * 2], vals[q * 8 + p * 2 + 1], ph[p], pl[p]);
            uint32_t off = (uint32_t)(b * 64 + q * 16);
            uint32_t so = SW64(off);
            *(uint4*)(Sh + so) = make_uint4(ph[0], ph[1], ph[2], ph[3]);
            *(uint4*)(Sl + so) = make_uint4(pl[0], pl[1], pl[2], pl[3]);
        }
    }
    __syncthreads();

    uint32_t sbh = smem_u32(Sh), sbl = smem_u32(Sl);
    uint32_t wbh = smem_u32(Wh), wbl = smem_u32(Wl);

    float acc[2][4][4];
#pragma unroll
    for (int mt = 0; mt < 2; mt++)
#pragma unroll
        for (int f = 0; f < 4; f++)
#pragma unroll
            for (int q = 0; q < 4; q++) acc[mt][f][q] = 0.0f;

#pragma unroll
    for (int ks = 0; ks < 2; ks++) {
        int cbA = ks * 32 + ((lane >> 4) << 4);
        uint32_t ah[2][4], al[2][4];
#pragma unroll
        for (int mt = 0; mt < 2; mt++) {
            int row = w * 32 + mt * 16 + (lane & 15);
            uint32_t off = SW64((uint32_t)(row * 64 + cbA));
            LDSM4(ah[mt], sbh + off);
            LDSM4(al[mt], sbl + off);
        }
        uint32_t bh[8], bl[8];
        int cbB = ks * 32 + (((lane >> 3) & 1) << 4);
#pragma unroll
        for (int g = 0; g < 2; g++) {
            int rowb = g * 16 + (lane & 7) + ((lane >> 4) << 3);
            uint32_t off = SW64((uint32_t)(rowb * 64 + cbB));
            LDSM4(bh + g * 4, wbh + off);
            LDSM4(bl + g * 4, wbl + off);
        }
#pragma unroll
        for (int mt = 0; mt < 2; mt++) {
#pragma unroll
            for (int f = 0; f < 4; f++) {
                MMA16816(acc[mt][f], ah[mt], bh[2 * f], bh[2 * f + 1]);
                MMA16816(acc[mt][f], ah[mt], bl[2 * f], bl[2 * f + 1]);
                MMA16816(acc[mt][f], al[mt], bh[2 * f], bh[2 * f + 1]);
            }
        }
    }

    int gid = lane >> 2, tig = lane & 3;
    float iT1 = invT[0], iT2 = invT[1];
#pragma unroll
    for (int mt = 0; mt < 2; mt++) {
#pragma unroll
        for (int rsel = 0; rsel < 2; rsel++) {
            float y0 = 0.0f, y1 = 0.0f;
#pragma unroll
            for (int f = 0; f < 2; f++) {
#pragma unroll
                for (int c2 = 0; c2 < 2; c2++) {
                    int h = f * 8 + tig * 2 + c2;
                    float xv = acc[mt][f][rsel * 2 + c2] + b1s[h];
                    float gv = acc[mt][f + 2][rsel * 2 + c2] + b1s[h + 16];
                    float u = (xv * iT1) * sigf(gv * iT1);
                    y0 += u * w2s[h * 2 + 0];
                    y1 += u * w2s[h * 2 + 1];
                }
            }
            y0 += __shfl_xor_sync(0xffffffffu, y0, 1);
            y0 += __shfl_xor_sync(0xffffffffu, y0, 2);
            y1 += __shfl_xor_sync(0xffffffffu, y1, 1);
            y1 += __shfl_xor_sync(0xffffffffu, y1, 2);
            if (tig == 0) {
                float fy0 = y0 + b2s[0];
                float fy1 = y1 + b2s[1];
                float r = (fy0 * iT2) * sigf(fy1 * iT2);
                int brow = w * 32 + mt * 16 + rsel * 8 + gid;
                g_hat[IT][(size_t)d * Bx + brow] = r;
                if (IT < 3) {
                    __nv_bfloat16 hh, ll;
                    split2(r, &hh, &ll);
                    size_t o = (size_t)brow * (DINx + Dx) + DINx + d;
                    g_prehi[o] = hh; g_prelo[o] = ll;
                }
            }
        }
    }
}

// ================= final assembly + synchrony =================
__global__ void __launch_bounds__(256) k_fin(
    float* __restrict__ out,
    const float* __restrict__ st_in, const float* __restrict__ at_in,
    const float* __restrict__ start_st, const float* __restrict__ start_at) {
    int tid = threadIdx.x;
    if (blockIdx.x < 1024) {
        __shared__ float hsm[4][32][9];
        int local = blockIdx.x;
        int dt = local & 127, bt = local >> 7;
        int d0 = dt * 8, b0 = bt * 32;
        {
            int j = tid >> 6, rem = tid & 63, bl = rem >> 1, hf = rem & 1;
            float4 hv = *(const float4*)&g_hst[j][(size_t)(b0 + bl) * Dx + d0 + hf * 4];
            hsm[j][bl][hf * 4 + 0] = hv.x;
            hsm[j][bl][hf * 4 + 1] = hv.y;
            hsm[j][bl][hf * 4 + 2] = hv.z;
            hsm[j][bl][hf * 4 + 3] = hv.w;
        }
        __syncthreads();
        int w = tid >> 5, lane = tid & 31;
        int d = d0 + w, b = b0 + lane;
        bool done = g_dones[b] != 0;
        const float* stp = done ? (start_st + d * 32) : (st_in + ((size_t)(b << 10) + d) * 32);
        const float* atp = done ? (start_at + d * 32) : (at_in + ((size_t)(b << 10) + d) * 32);
        float so[32], ao[32];
#pragma unroll
        for (int q = 1; q < 8; q++) {
            float4 t4 = ((const float4*)stp)[q];
            so[q * 4 - 4] = t4.x; so[q * 4 - 3] = t4.y; so[q * 4 - 2] = t4.z; so[q * 4 - 1] = t4.w;
            float4 u4 = ((const float4*)atp)[q];
            ao[q * 4 - 4] = u4.x; ao[q * 4 - 3] = u4.y; ao[q * 4 - 2] = u4.z; ao[q * 4 - 1] = u4.w;
        }
#pragma unroll
        for (int j = 0; j < 4; j++) {
            so[28 + j] = hsm[j][lane][w];
            ao[28 + j] = g_hat[j][(size_t)d * Bx + b];
        }
        float* o1 = out + ((size_t)(b << 10) + d) * 32;
        float* o2 = o1 + BDMx;
#pragma unroll
        for (int q = 0; q < 8; q++) {
            float4 v1 = { so[q * 4], so[q * 4 + 1], so[q * 4 + 2], so[q * 4 + 3] };
            float4 v2 = { ao[q * 4], ao[q * 4 + 1], ao[q * 4 + 2], ao[q * 4 + 3] };
            ((float4*)o1)[q] = v1;
            ((float4*)o2)[q] = v2;
        }
    } else {
        __shared__ float S[Mx * NSYx];
        int b = blockIdx.x - 1024;
        bool done = g_dones[b] != 0;
        float* outs = out + 2 * (size_t)BDMx;
        for (int t = tid; t < Mx * NSYx; t += 256) {
            int m = t & 31, j = t >> 5;
            int dd = Dx - NSYx + j;
            float val;
            if (m < 28)
                val = done ? start_at[dd * 32 + m + 4]
                           : at_in[((size_t)(b * Dx + dd)) * 32 + m + 4];
            else
                val = g_hat[m - 28][(size_t)dd * Bx + b];
            S[m * NSYx + j] = val;
        }
        __syncthreads();
        for (int s = tid; s < SYNCHx; s += 256) {
            int ti = g_tri_i[s], tj = g_tri_j[s];
            float acc = 0.0f;
#pragma unroll
            for (int m = 0; m < Mx; m++)
                acc += g_decay[m * SYNCHx + s] * S[m * NSYx + ti] * S[m * NSYx + tj];
            outs[(size_t)b * SYNCHx + s] = acc * g_invden[s];
        }
    }
}

// =====================================================================
extern "C" void kernel_launch(void* const* d_in, const int* in_sizes, int n_in,
                              void* d_out, int out_size) {
    (void)in_sizes; (void)n_in; (void)out_size;
    const float* obs      = (const float*)d_in[0];
    const unsigned char* dones_raw = (const unsigned char*)d_in[1];
    const float* st_in    = (const float*)d_in[3];
    const float* at_in    = (const float*)d_in[4];
    const float* start_st = (const float*)d_in[5];
    const float* start_at = (const float*)d_in[6];
    const float* bb_w1    = (const float*)d_in[7];
    const float* bb_b1    = (const float*)d_in[8];
    const float* ln1s     = (const float*)d_in[9];
    const float* ln1b     = (const float*)d_in[10];
    const float* bb_w2    = (const float*)d_in[11];
    const float* bb_b2    = (const float*)d_in[12];
    const float* ln2s     = (const float*)d_in[13];
    const float* ln2b     = (const float*)d_in[14];
    const float* syn_w1   = (const float*)d_in[15];
    const float* syn_b1   = (const float*)d_in[16];
    const float* sln1s    = (const float*)d_in[17];
    const float* sln1b    = (const float*)d_in[18];
    const float* syn_w2   = (const float*)d_in[19];
    const float* syn_b2   = (const float*)d_in[20];
    const float* sln2s    = (const float*)d_in[21];
    const float* sln2b    = (const float*)d_in[22];
    const float* nlm1_w   = (const float*)d_in[23];
    const float* nlm1_b   = (const float*)d_in[24];
    const float* nlm1_T   = (const float*)d_in[25];
    const float* nlm2_w   = (const float*)d_in[26];
    const float* nlm2_b   = (const float*)d_in[27];
    const float* nlm2_T   = (const float*)d_in[28];
    const float* decay_p  = (const float*)d_in[29];
    float* out = (float*)d_out;

    void *p_y, *p_hst;
    void *p_obshi, *p_obslo, *p_prehi, *p_prelo, *p_h1hi, *p_h1lo;
    void *p_wb1h, *p_wb1l, *p_wb2h, *p_wb2l, *p_ws1h, *p_ws1l, *p_ws2h, *p_ws2l;
    cudaGetSymbolAddress(&p_y, g_y);
    cudaGetSymbolAddress(&p_hst, g_hst);
    cudaGetSymbolAddress(&p_obshi, g_obshi);  cudaGetSymbolAddress(&p_obslo, g_obslo);
    cudaGetSymbolAddress(&p_prehi, g_prehi);  cudaGetSymbolAddress(&p_prelo, g_prelo);
    cudaGetSymbolAddress(&p_h1hi, g_h1hi);    cudaGetSymbolAddress(&p_h1lo, g_h1lo);
    cudaGetSymbolAddress(&p_wb1h, g_wb1hi);   cudaGetSymbolAddress(&p_wb1l, g_wb1lo);
    cudaGetSymbolAddress(&p_wb2h, g_wb2hi);   cudaGetSymbolAddress(&p_wb2l, g_wb2lo);
    cudaGetSymbolAddress(&p_ws1h, g_ws1hi);   cudaGetSymbolAddress(&p_ws1l, g_ws1lo);
    cudaGetSymbolAddress(&p_ws2h, g_ws2hi);   cudaGetSymbolAddress(&p_ws2l, g_ws2lo);
    float* gy   = (float*)p_y;
    float* ghst = (float*)p_hst;

    static int init_done = 0;
    static cudaStream_t s_side = nullptr;
    static cudaEvent_t ev_fork = nullptr, ev_join = nullptr;
    int gsmem = GSTAGES * GBUF_BYTES + 1024;
    if (!init_done) {
        cudaFuncSetAttribute(k_tgemm, cudaFuncAttributeMaxDynamicSharedMemorySize, gsmem);
        cudaStreamCreateWithFlags(&s_side, cudaStreamNonBlocking);
        cudaEventCreateWithFlags(&ev_fork, cudaEventDisableTiming);
        cudaEventCreateWithFlags(&ev_join, cudaEventDisableTiming);
        init_done = 1;
    }

    // fork: side branch preps NLM + synapse weights
    cudaEventRecord(ev_fork, 0);
    cudaStreamWaitEvent(s_side, ev_fork, 0);
    k_prep_side<<<9216, 256, 0, s_side>>>(nlm1_w, nlm2_w, syn_w1, syn_w2);
    cudaEventRecord(ev_join, s_side);

    // main branch: light prep + backbone
    k_prep_main<<<1034, 256>>>(dones_raw, decay_p, obs, bb_w1, bb_w2);

    k_tgemm<<<dim3(16, 4, 2), 256, gsmem>>>(
        (const __nv_bfloat16*)p_obshi, (const __nv_bfloat16*)p_obslo,
        (const __nv_bfloat16*)p_wb1h, (const __nv_bfloat16*)p_wb1l,
        gy, 0, 128, 256, 256, 1024);
    k_gluln_split<2><<<Bx, 512>>>(gy, 512, bb_b1, ln1s, ln1b,
        (__nv_bfloat16*)p_h1hi, (__nv_bfloat16*)p_h1lo, 512, 0, nullptr, nullptr);
    k_tgemm<<<dim3(16, 4, 2), 256, gsmem>>>(
        (const __nv_bfloat16*)p_h1hi, (const __nv_bfloat16*)p_h1lo,
        (const __nv_bfloat16*)p_wb2h, (const __nv_bfloat16*)p_wb2l,
        gy, 0, 256, 512, 512, 1024);
    k_gluln_split<2><<<Bx, 512>>>(gy, 512, bb_b2, ln2s, ln2b,
        (__nv_bfloat16*)p_prehi, (__nv_bfloat16*)p_prelo, 1536, 1, at_in, start_at);

    // join: synapse + NLM weights ready
    cudaStreamWaitEvent(0, ev_join, 0);

    // hoisted f-part of synapse GEMM1 (iteration-invariant): K=0..512 -> slice 2
    k_tgemm<<<dim3(32, 4, 1), 256, gsmem>>>(
        (const __nv_bfloat16*)p_prehi, (const __nv_bfloat16*)p_prelo,
        (const __nv_bfloat16*)p_ws1h, (const __nv_bfloat16*)p_ws1l,
        gy + 2 * (size_t)Bx * 2048, 0, 512, 1536, 1536, 2048);

    for (int i = 0; i < ITERSx; i++) {
        // synapse GEMM1, at-part only: K=512..1536, KS=2
        k_tgemm<<<dim3(32, 4, 2), 256, gsmem>>>(
            (const __nv_bfloat16*)p_prehi, (const __nv_bfloat16*)p_prelo,
            (const __nv_bfloat16*)p_ws1h, (const __nv_bfloat16*)p_ws1l,
            gy, 512, 512, 1536, 1536, 2048);
        k_gluln_split<3><<<Bx, 1024>>>(gy, 1024, syn_b1, sln1s, sln1b,
            (__nv_bfloat16*)p_h1hi, (__nv_bfloat16*)p_h1lo, 1024, 0, nullptr, nullptr);
        // synapse GEMM2 K=1024, KS=2
        k_tgemm<<<dim3(32, 4, 2), 256, gsmem>>>(
            (const __nv_bfloat16*)p_h1hi, (const __nv_bfloat16*)p_h1lo,
            (const __nv_bfloat16*)p_ws2h, (const __nv_bfloat16*)p_ws2l,
            gy, 0, 512, 1024, 1024, 2048);
        k_gluln_f32<2><<<Bx, 1024>>>(gy, 1024, syn_b2, sln2s, sln2b,
            ghst + (size_t)i * BDx);
        switch (i) {
            case 0: k_nlm_tc<0><<<1024, 256>>>(st_in, start_st, nlm1_b, nlm1_T, nlm2_b, nlm2_T); break;
            case 1: k_nlm_tc<1><<<1024, 256>>>(st_in, start_st, nlm1_b, nlm1_T, nlm2_b, nlm2_T); break;
            case 2: k_nlm_tc<2><<<1024, 256>>>(st_in, start_st, nlm1_b, nlm1_T, nlm2_b, nlm2_T); break;
            case 3: k_nlm_tc<3><<<1024, 256>>>(st_in, start_st, nlm1_b, nlm1_T, nlm2_b, nlm2_T); break;
        }
    }

    k_fin<<<1024 + Bx, 256>>>(out, st_in, at_in, start_st, start_at);
}

// round 16
// speedup vs baseline: 1.4865x; 1.0435x over previous
#include <cuda_runtime.h>
#include <cuda_bf16.h>
#include <math.h>
#include <stdint.h>

#define Bx    256
#define OBSx  256
#define DINx  512
#define Dx    1024
#define Mx    32
#define HIDx  16
#define NSYx  64
#define ITERSx 4
#define SYNCHx 2080
#define BDx   (Bx * Dx)          // 262144
#define BDMx  (Bx * Dx * Mx)     // 8388608

// ---------------- scratch (static device globals) ----------------
__device__ float g_y[4 * Bx * 2 * Dx];               // split-K partial slices
__device__ __align__(16) __nv_bfloat16 g_w1bh[Dx * 1024];  // [d][h*32+m] bf16 hi
__device__ __align__(16) __nv_bfloat16 g_w1bl[Dx * 1024];  // [d][h*32+m] bf16 lo
__device__ float g_w2t[Dx * 32];
__device__ float g_decay[Mx * SYNCHx];
__device__ float g_invden[SYNCHx];
__device__ int   g_tri_i[SYNCHx];
__device__ int   g_tri_j[SYNCHx];
__device__ int   g_dones[Bx];
__device__ __align__(16) float g_hst[ITERSx][BDx];   // [i][b*1024+d]
__device__ __align__(16) float g_hstT[ITERSx][BDx];  // [i][d*256+b] (coalesced mirror)
__device__ __align__(16) float g_hat[ITERSx][BDx];   // [i][d*256+b]

__device__ __align__(256) __nv_bfloat16 g_obshi[Bx * OBSx];
__device__ __align__(256) __nv_bfloat16 g_obslo[Bx * OBSx];
__device__ __align__(256) __nv_bfloat16 g_prehi[Bx * (DINx + Dx)];
__device__ __align__(256) __nv_bfloat16 g_prelo[Bx * (DINx + Dx)];
__device__ __align__(256) __nv_bfloat16 g_h1hi[Bx * Dx];
__device__ __align__(256) __nv_bfloat16 g_h1lo[Bx * Dx];
__device__ __align__(256) __nv_bfloat16 g_wb1hi[1024 * 256];
__device__ __align__(256) __nv_bfloat16 g_wb1lo[1024 * 256];
__device__ __align__(256) __nv_bfloat16 g_wb2hi[1024 * 512];
__device__ __align__(256) __nv_bfloat16 g_wb2lo[1024 * 512];
__device__ __align__(256) __nv_bfloat16 g_ws1hi[2048 * 1536];
__device__ __align__(256) __nv_bfloat16 g_ws1lo[2048 * 1536];
__device__ __align__(256) __nv_bfloat16 g_ws2hi[2048 * 1024];
__device__ __align__(256) __nv_bfloat16 g_ws2lo[2048 * 1024];

__device__ __forceinline__ float sigf(float x) {
    return __fdividef(1.0f, 1.0f + __expf(-x));
}
__device__ __forceinline__ void split2(float v, __nv_bfloat16* h, __nv_bfloat16* l) {
    __nv_bfloat16 hh = __float2bfloat16(v);
    *h = hh;
    *l = __float2bfloat16(v - __bfloat162float(hh));
}
__device__ __forceinline__ void split_pack(float v0, float v1, uint32_t& ph, uint32_t& pl) {
    __nv_bfloat16 h0 = __float2bfloat16(v0);
    __nv_bfloat16 h1 = __float2bfloat16(v1);
    __nv_bfloat16 l0 = __float2bfloat16(v0 - __bfloat162float(h0));
    __nv_bfloat16 l1 = __float2bfloat16(v1 - __bfloat162float(h1));
    unsigned short u0, u1;
    memcpy(&u0, &h0, 2); memcpy(&u1, &h1, 2);
    ph = (uint32_t)u0 | ((uint32_t)u1 << 16);
    memcpy(&u0, &l0, 2); memcpy(&u1, &l1, 2);
    pl = (uint32_t)u0 | ((uint32_t)u1 << 16);
}

// ================= PTX helpers =================
__device__ __forceinline__ uint32_t smem_u32(const void* p) {
    uint32_t a;
    asm("{ .reg .u64 t; cvta.to.shared.u64 t, %1; cvt.u32.u64 %0, t; }" : "=r"(a) : "l"(p));
    return a;
}
#define SW128(off) ((off) ^ (((off) >> 3) & 0x70))
#define SW64(off)  ((off) ^ (((off) >> 3) & 0x30))
#define CP_ASYNC16(dst, src) \
    asm volatile("cp.async.cg.shared.global [%0], [%1], 16;" :: "r"(dst), "l"(src))
#define CP_COMMIT()  asm volatile("cp.async.commit_group;" ::: "memory")
#define CP_WAIT(n)   asm volatile("cp.async.wait_group %0;" :: "n"(n) : "memory")
#define LDSM4(r, addr) \
    asm volatile("ldmatrix.sync.aligned.m8n8.x4.shared.b16 {%0,%1,%2,%3}, [%4];" \
        : "=r"((r)[0]), "=r"((r)[1]), "=r"((r)[2]), "=r"((r)[3]) : "r"(addr))
#define MMA16816(acc, a, b0, b1) \
    asm volatile("mma.sync.aligned.m16n8k16.row.col.f32.bf16.bf16.f32 " \
        "{%0,%1,%2,%3}, {%4,%5,%6,%7}, {%8,%9}, {%0,%1,%2,%3};" \
        : "+f"((acc)[0]), "+f"((acc)[1]), "+f"((acc)[2]), "+f"((acc)[3]) \
        : "r"((a)[0]), "r"((a)[1]), "r"((a)[2]), "r"((a)[3]), "r"(b0), "r"(b1))

// ================= split-bf16 HMMA GEMM, split-K with K-base offset =========
#define GBUF_BYTES 32768
#define GSTAGES 3
__global__ void __launch_bounds__(256) k_tgemm(
    const __nv_bfloat16* __restrict__ Ahi, const __nv_bfloat16* __restrict__ Alo,
    const __nv_bfloat16* __restrict__ Bhi, const __nv_bfloat16* __restrict__ Blo,
    float* __restrict__ C, int kbase, int Kloc, int lda, int ldb, int N)
{
    extern __shared__ char smem_raw[];
    uint32_t sbase = smem_u32(smem_raw);
    uint32_t abase = (sbase + 1023u) & ~1023u;

    int tid = threadIdx.x;
    int lane = tid & 31;
    int wid = tid >> 5;
    int warp_m = wid & 1;
    int warp_n = wid >> 1;
    int row0 = blockIdx.y * 64;
    int col0 = blockIdx.x * 64;
    int koff = kbase + blockIdx.z * Kloc;
    int NC = Kloc >> 6;

    float acc[2][2][4];
#pragma unroll
    for (int i = 0; i < 2; i++)
#pragma unroll
        for (int j = 0; j < 2; j++)
#pragma unroll
            for (int q = 0; q < 4; q++) acc[i][j][q] = 0.0f;

    auto load_chunk = [&](int buf, int k0) {
        uint32_t bb = abase + buf * GBUF_BYTES;
#pragma unroll
        for (int i = 0; i < 2; i++) {
            int u = tid + i * 256;
            int r = u >> 3, ch = u & 7;
            uint32_t soff = SW128((uint32_t)(r * 128 + ch * 16));
            size_t goA = (size_t)(row0 + r) * lda + koff + k0 + ch * 8;
            size_t goB = (size_t)(col0 + r) * ldb + koff + k0 + ch * 8;
            CP_ASYNC16(bb + soff,          Ahi + goA);
            CP_ASYNC16(bb + 8192 + soff,   Alo + goA);
            CP_ASYNC16(bb + 16384 + soff,  Bhi + goB);
            CP_ASYNC16(bb + 24576 + soff,  Blo + goB);
        }
    };

    load_chunk(0, 0);
    CP_COMMIT();
    load_chunk(1, 64);
    CP_COMMIT();

    int a_r = warp_m * 32 + (lane & 15);
    int a_csel = (lane >> 4) << 3;
    int b_r = warp_n * 16 + (lane & 7) + ((lane >> 4) << 3);
    int b_csel = ((lane >> 3) & 1) << 3;

    int buf = 0, pbuf = 2;
    for (int c = 0; c < NC; c++) {
        CP_WAIT(GSTAGES - 2);
        __syncthreads();
        if (c + 2 < NC) load_chunk(pbuf, (c + 2) * 64);
        CP_COMMIT();

        uint32_t bb = abase + buf * GBUF_BYTES;
#pragma unroll
        for (int kk = 0; kk < 4; kk++) {
            int k0 = kk * 16;
            uint32_t ah[2][4], al[2][4], bh[4], bl[4];
#pragma unroll
            for (int mf = 0; mf < 2; mf++) {
                uint32_t off = SW128((uint32_t)((a_r + mf * 16) * 128 + (k0 + a_csel) * 2));
                LDSM4(ah[mf], bb + off);
                LDSM4(al[mf], bb + 8192 + off);
            }
            {
                uint32_t off = SW128((uint32_t)(b_r * 128 + (k0 + b_csel) * 2));
                LDSM4(bh, bb + 16384 + off);
                LDSM4(bl, bb + 24576 + off);
            }
#pragma unroll
            for (int mf = 0; mf < 2; mf++) {
#pragma unroll
                for (int nf = 0; nf < 2; nf++) {
                    MMA16816(acc[mf][nf], ah[mf], bh[2 * nf], bh[2 * nf + 1]);
                    MMA16816(acc[mf][nf], ah[mf], bl[2 * nf], bl[2 * nf + 1]);
                    MMA16816(acc[mf][nf], al[mf], bh[2 * nf], bh[2 * nf + 1]);
                }
            }
        }
        buf = (buf == GSTAGES - 1) ? 0 : buf + 1;
        pbuf = (pbuf == GSTAGES - 1) ? 0 : pbuf + 1;
    }

    float* Cz = C + (size_t)blockIdx.z * Bx * N;
    int gid = lane >> 2, tig = lane & 3;
#pragma unroll
    for (int mf = 0; mf < 2; mf++) {
#pragma unroll
        for (int nf = 0; nf < 2; nf++) {
            int r = row0 + warp_m * 32 + mf * 16 + gid;
            int cc = col0 + warp_n * 16 + nf * 8 + tig * 2;
            float2 o0 = { acc[mf][nf][0], acc[mf][nf][1] };
            float2 o1 = { acc[mf][nf][2], acc[mf][nf][3] };
            *(float2*)&Cz[(size_t)r * N + cc] = o0;
            *(float2*)&Cz[(size_t)(r + 8) * N + cc] = o1;
        }
    }
}

// ================= prep kernels (main + side branch) =================
__device__ void tsplit_block(const float* __restrict__ W, int K, int N,
                             __nv_bfloat16* __restrict__ Ohi, __nv_bfloat16* __restrict__ Olo,
                             int local) {
    __shared__ float t[32][33];
    int ktiles = K >> 5;
    int kt = local % ktiles, nt = local / ktiles;
    int k0 = kt * 32, n0 = nt * 32;
    int tx = threadIdx.x & 31, ty = threadIdx.x >> 5;
    for (int i = ty; i < 32; i += 8)
        t[i][tx] = W[(size_t)(k0 + i) * N + n0 + tx];
    __syncthreads();
    for (int i = ty; i < 32; i += 8) {
        float v = t[tx][i];
        size_t o = (size_t)(n0 + i) * K + k0 + tx;
        __nv_bfloat16 h, l;
        split2(v, &h, &l);
        Ohi[o] = h; Olo[o] = l;
    }
}

__global__ void __launch_bounds__(256) k_prep_main(
    const unsigned char* __restrict__ dones_raw,
    const float* __restrict__ dp,
    const float* __restrict__ obs,
    const float* __restrict__ bw1, const float* __restrict__ bw2) {
    int bid = blockIdx.x, tid = threadIdx.x;
    if (bid == 0) {
        __shared__ int mode;
        if (tid == 0) {
            bool nzoff = false, floatlike = true, anynz = false;
            for (int i = 0; i < Bx; i++) {
                unsigned char v = dones_raw[i];
                if (v) {
                    anynz = true;
                    int r = i & 3;
                    if (r != 0) nzoff = true;
                    bool okf = (r == 2 && v == 0x80) || (r == 3 && v == 0x3F);
                    if (!okf) floatlike = false;
                }
            }
            mode = (nzoff && floatlike && anynz) ? 2 : (nzoff ? 0 : 1);
        }
        __syncthreads();
        int b = tid, m = mode, v;
        if (m == 0)      v = (dones_raw[b] != 0);
        else if (m == 1) v = (((const int*)dones_raw)[b] != 0);
        else             v = (((const float*)dones_raw)[b] != 0.0f);
        g_dones[b] = v;
    } else if (bid < 10) {
        int s = (bid - 1) * 256 + tid;
        if (s < SYNCHx) {
            float c = fminf(fmaxf(dp[s], 0.0f), 4.0f);
            float sum = 0.0f;
            for (int m = 0; m < Mx; m++) {
                float v = __expf(-(float)(Mx - 1 - m) * c);
                g_decay[m * SYNCHx + s] = v;
                sum += v;
            }
            g_invden[s] = rsqrtf(sum);
            int i = 0, base = 0;
            while (s >= base + (NSYx - i)) { base += NSYx - i; i++; }
            g_tri_i[s] = i;
            g_tri_j[s] = i + (s - base);
        }
    } else if (bid < 266) {
        int i = (bid - 10) * 256 + tid;
        split2(obs[i], &g_obshi[i], &g_obslo[i]);
    } else if (bid < 522) {
        tsplit_block(bw1, 256, 1024, g_wb1hi, g_wb1lo, bid - 266);
    } else {
        tsplit_block(bw2, 512, 1024, g_wb2hi, g_wb2lo, bid - 522);
    }
}

__global__ void __launch_bounds__(256) k_prep_side(
    const float* __restrict__ nw1, const float* __restrict__ nw2,
    const float* __restrict__ sw1, const float* __restrict__ sw2) {
    int bid = blockIdx.x, tid = threadIdx.x;
    if (bid < 4096) {
        int idx = bid * 256 + tid;
        int d = idx >> 10, hm = idx & 1023;
        int h = hm >> 5, m = hm & 31;
        float v = nw1[(m * 32 + h) * Dx + d];
        split2(v, &g_w1bh[idx], &g_w1bl[idx]);
        if (idx < Dx * 32) {
            int d2 = idx >> 5, hc = idx & 31;
            g_w2t[idx] = nw2[hc * Dx + d2];
        }
    } else if (bid < 7168) {
        tsplit_block(sw1, 1536, 2048, g_ws1hi, g_ws1lo, bid - 4096);
    } else {
        tsplit_block(sw2, 1024, 2048, g_ws2hi, g_ws2lo, bid - 7168);
    }
}

// ====== GLU + LN (sums KS split-K partials + bias) -> bf16 split ======
template<int KS>
__global__ void __launch_bounds__(1024) k_gluln_split(
    const float* __restrict__ y, int halfN,
    const float* __restrict__ bias,
    const float* __restrict__ sc, const float* __restrict__ bi,
    __nv_bfloat16* __restrict__ ohi, __nv_bfloat16* __restrict__ olo,
    int ostride, int gather,
    const float* __restrict__ at_in,
    const float* __restrict__ start_at) {
    __shared__ float red_s[32], red_q[32];
    int row = blockIdx.x, tid = threadIdx.x;
    int nw = blockDim.x >> 5;
    size_t rstride = (size_t)Bx * 2 * halfN;
    const float* yr = y + (size_t)row * 2 * halfN;
    int c = tid;
    float av[KS], gv[KS];
#pragma unroll
    for (int z = 0; z < KS; z++) {
        av[z] = yr[z * rstride + c];
        gv[z] = yr[z * rstride + halfN + c];
    }
    float a = bias[c];
    float g = bias[halfN + c];
#pragma unroll
    for (int z = 0; z < KS; z++) { a += av[z]; g += gv[z]; }
    float val = a * sigf(g);

    if (gather) {
        bool done = g_dones[row] != 0;
        for (int cc = tid; cc < Dx; cc += blockDim.x) {
            float v2 = done ? start_at[cc * 32 + 31]
                            : at_in[((size_t)(row * Dx + cc)) * 32 + 31];
            size_t o = (size_t)row * ostride + halfN + cc;
            split2(v2, &ohi[o], &olo[o]);
        }
    }

    float sum = val, sq = val * val;
#pragma unroll
    for (int o = 16; o > 0; o >>= 1) {
        sum += __shfl_xor_sync(0xffffffffu, sum, o);
        sq  += __shfl_xor_sync(0xffffffffu, sq, o);
    }
    int w = tid >> 5;
    int lane = tid & 31;
    if (lane == 0) { red_s[w] = sum; red_q[w] = sq; }
    __syncthreads();
    if (w == 0) {
        float ts = (lane < nw) ? red_s[lane] : 0.0f;
        float tq = (lane < nw) ? red_q[lane] : 0.0f;
#pragma unroll
        for (int o = 16; o > 0; o >>= 1) {
            ts += __shfl_xor_sync(0xffffffffu, ts, o);
            tq += __shfl_xor_sync(0xffffffffu, tq, o);
        }
        if (lane == 0) { red_s[0] = ts; red_q[0] = tq; }
    }
    __syncthreads();
    float invN = 1.0f / (float)halfN;
    float mean = red_s[0] * invN;
    float var = red_q[0] * invN - mean * mean;
    float inv = rsqrtf(var + 1e-6f);
    {
        float o_ = (val - mean) * inv * sc[c] + bi[c];
        size_t o = (size_t)row * ostride + c;
        split2(o_, &ohi[o], &olo[o]);
    }
}

// GLU + LN -> fp32 contiguous (h_st[i]); blockDim==halfN; KS compile-time
template<int KS>
__global__ void __launch_bounds__(1024) k_gluln_f32(
    const float* __restrict__ y, int halfN,
    const float* __restrict__ bias,
    const float* __restrict__ sc, const float* __restrict__ bi,
    float* __restrict__ out) {
    __shared__ float red_s[32], red_q[32];
    int row = blockIdx.x, tid = threadIdx.x;
    int nw = blockDim.x >> 5;
    size_t rstride = (size_t)Bx * 2 * halfN;
    const float* yr = y + (size_t)row * 2 * halfN;
    int c = tid;
    float av[KS], gv[KS];
#pragma unroll
    for (int z = 0; z < KS; z++) {
        av[z] = yr[z * rstride + c];
        gv[z] = yr[z * rstride + halfN + c];
    }
    float a = bias[c];
    float g = bias[halfN + c];
#pragma unroll
    for (int z = 0; z < KS; z++) { a += av[z]; g += gv[z]; }
    float val = a * sigf(g);
    float sum = val, sq = val * val;
#pragma unroll
    for (int o = 16; o > 0; o >>= 1) {
        sum += __shfl_xor_sync(0xffffffffu, sum, o);
        sq  += __shfl_xor_sync(0xffffffffu, sq, o);
    }
    int w = tid >> 5;
    int lane = tid & 31;
    if (lane == 0) { red_s[w] = sum; red_q[w] = sq; }
    __syncthreads();
    if (w == 0) {
        float ts = (lane < nw) ? red_s[lane] : 0.0f;
        float tq = (lane < nw) ? red_q[lane] : 0.0f;
#pragma unroll
        for (int o = 16; o > 0; o >>= 1) {
            ts += __shfl_xor_sync(0xffffffffu, ts, o);
            tq += __shfl_xor_sync(0xffffffffu, tq, o);
        }
        if (lane == 0) { red_s[0] = ts; red_q[0] = tq; }
    }
    __syncthreads();
    float invN = 1.0f / (float)halfN;
    float mean = red_s[0] * invN;
    float var = red_q[0] * invN - mean * mean;
    float inv = rsqrtf(var + 1e-6f);
    out[(size_t)row * halfN + c] = (val - mean) * inv * sc[c] + bi[c];
}

// ================= NLM via tensor cores (one d per block) =================
template<int IT>
__global__ void __launch_bounds__(256) k_nlm_tc(
    const float* __restrict__ st_in, const float* __restrict__ start_st,
    const float* __restrict__ b1, const float* __restrict__ T1,
    const float* __restrict__ b2, const float* __restrict__ T2) {
    __shared__ __align__(16) uint8_t Sh[16384], Sl[16384];
    __shared__ __align__(16) uint8_t Wh[2048], Wl[2048];
    __shared__ float w2s[32], b1s[32], b2s[2], invT[2];
    int tid = threadIdx.x;
    int lane = tid & 31;
    int w = tid >> 5;
    int d = blockIdx.x;

    if (tid < 128) {
        uint4 vh = ((const uint4*)(g_w1bh + (size_t)d * 1024))[tid];
        uint4 vl = ((const uint4*)(g_w1bl + (size_t)d * 1024))[tid];
        uint32_t off = (uint32_t)tid * 16;
        uint32_t so = SW64(off);
        *(uint4*)(Wh + so) = vh;
        *(uint4*)(Wl + so) = vl;
    }
    if (tid < 32) { w2s[tid] = g_w2t[d * 32 + tid]; b1s[tid] = b1[d * 32 + tid]; }
    if (tid < 2)  b2s[tid] = b2[d * 2 + tid];
    if (tid == 0) { invT[0] = 1.0f / T1[0]; invT[1] = 1.0f / T2[0]; }

    {
        int b = tid;
        const float* stp = g_dones[b] ? (start_st + d * 32)
                                      : (st_in + ((size_t)(b << 10) + d) * 32);
        float sar[32];
#pragma unroll
        for (int q = 0; q < 8; q++) {
            float4 t4 = ((const float4*)stp)[q];
            sar[q * 4 + 0] = t4.x; sar[q * 4 + 1] = t4.y;
            sar[q * 4 + 2] = t4.z; sar[q * 4 + 3] = t4.w;
        }
        float vals[32];
#pragma unroll
        for (int k = 0; k < 31 - IT; k++) vals[k] = sar[k + IT + 1];
        // older history arrays: coalesced transposed mirror
#pragma unroll
        for (int j = 0; j < IT; j++) vals[31 - IT + j] = g_hstT[j][(size_t)d * Bx + b];
        // fresh array from gluln (row-major), then publish coalesced mirror
        {
            float hv = g_hst[IT][(size_t)b * 1024 + d];
            vals[31] = hv;
            g_hstT[IT][(size_t)d * Bx + b] = hv;
        }
#pragma unroll
        for (int q = 0; q < 4; q++) {
            uint32_t ph[4], pl[4];
#pragma unroll
            for (int p = 0; p < 4; p++)
                split_pack(vals[q * 8 + p * 2], vals[q * 8 + p * 2 + 1], ph[p], pl[p]);
            uint32_t off = (uint32_t)(b * 64 + q * 16);
            uint32_t so = SW64(off);
            *(uint4*)(Sh + so) = make_uint4(ph[0], ph[1], ph[2], ph[3]);
            *(uint4*)(Sl + so) = make_uint4(pl[0], pl[1], pl[2], pl[3]);
        }
    }
    __syncthreads();

    uint32_t sbh = smem_u32(Sh), sbl = smem_u32(Sl);
    uint32_t wbh = smem_u32(Wh), wbl = smem_u32(Wl);

    float acc[2][4][4];
#pragma unroll
    for (int mt = 0; mt < 2; mt++)
#pragma unroll
        for (int f = 0; f < 4; f++)
#pragma unroll
            for (int q = 0; q < 4; q++) acc[mt][f][q] = 0.0f;

#pragma unroll
    for (int ks = 0; ks < 2; ks++) {
        int cbA = ks * 32 + ((lane >> 4) << 4);
        uint32_t ah[2][4], al[2][4];
#pragma unroll
        for (int mt = 0; mt < 2; mt++) {
            int row = w * 32 + mt * 16 + (lane & 15);
            uint32_t off = SW64((uint32_t)(row * 64 + cbA));
            LDSM4(ah[mt], sbh + off);
            LDSM4(al[mt], sbl + off);
        }
        uint32_t bh[8], bl[8];
        int cbB = ks * 32 + (((lane >> 3) & 1) << 4);
#pragma unroll
        for (int g = 0; g < 2; g++) {
            int rowb = g * 16 + (lane & 7) + ((lane >> 4) << 3);
            uint32_t off = SW64((uint32_t)(rowb * 64 + cbB));
            LDSM4(bh + g * 4, wbh + off);
            LDSM4(bl + g * 4, wbl + off);
        }
#pragma unroll
        for (int mt = 0; mt < 2; mt++) {
#pragma unroll
            for (int f = 0; f < 4; f++) {
                MMA16816(acc[mt][f], ah[mt], bh[2 * f], bh[2 * f + 1]);
                MMA16816(acc[mt][f], ah[mt], bl[2 * f], bl[2 * f + 1]);
                MMA16816(acc[mt][f], al[mt], bh[2 * f], bh[2 * f + 1]);
            }
        }
    }

    int gid = lane >> 2, tig = lane & 3;
    float iT1 = invT[0], iT2 = invT[1];
#pragma unroll
    for (int mt = 0; mt < 2; mt++) {
#pragma unroll
        for (int rsel = 0; rsel < 2; rsel++) {
            float y0 = 0.0f, y1 = 0.0f;
#pragma unroll
            for (int f = 0; f < 2; f++) {
#pragma unroll
                for (int c2 = 0; c2 < 2; c2++) {
                    int h = f * 8 + tig * 2 + c2;
                    float xv = acc[mt][f][rsel * 2 + c2] + b1s[h];
                    float gv = acc[mt][f + 2][rsel * 2 + c2] + b1s[h + 16];
                    float u = (xv * iT1) * sigf(gv * iT1);
                    y0 += u * w2s[h * 2 + 0];
                    y1 += u * w2s[h * 2 + 1];
                }
            }
            y0 += __shfl_xor_sync(0xffffffffu, y0, 1);
            y0 += __shfl_xor_sync(0xffffffffu, y0, 2);
            y1 += __shfl_xor_sync(0xffffffffu, y1, 1);
            y1 += __shfl_xor_sync(0xffffffffu, y1, 2);
            if (tig == 0) {
                float fy0 = y0 + b2s[0];
                float fy1 = y1 + b2s[1];
                float r = (fy0 * iT2) * sigf(fy1 * iT2);
                int brow = w * 32 + mt * 16 + rsel * 8 + gid;
                g_hat[IT][(size_t)d * Bx + brow] = r;
                if (IT < 3) {
                    __nv_bfloat16 hh, ll;
                    split2(r, &hh, &ll);
                    size_t o = (size_t)brow * (DINx + Dx) + DINx + d;
                    g_prehi[o] = hh; g_prelo[o] = ll;
                }
            }
        }
    }
}

// ================= final assembly: st half (overlaps nlm<3>) =================
__global__ void __launch_bounds__(256) k_fin_st(
    float* __restrict__ out,
    const float* __restrict__ st_in, const float* __restrict__ start_st) {
    int tid = threadIdx.x;
    __shared__ float hsm[4][32][9];
    int local = blockIdx.x;
    int dt = local & 127, bt = local >> 7;
    int d0 = dt * 8, b0 = bt * 32;
    {
        int j = tid >> 6, rem = tid & 63, bl = rem >> 1, hf = rem & 1;
        float4 hv = *(const float4*)&g_hst[j][(size_t)(b0 + bl) * Dx + d0 + hf * 4];
        hsm[j][bl][hf * 4 + 0] = hv.x;
        hsm[j][bl][hf * 4 + 1] = hv.y;
        hsm[j][bl][hf * 4 + 2] = hv.z;
        hsm[j][bl][hf * 4 + 3] = hv.w;
    }
    __syncthreads();
    int w = tid >> 5, lane = tid & 31;
    int d = d0 + w, b = b0 + lane;
    bool done = g_dones[b] != 0;
    const float* stp = done ? (start_st + d * 32) : (st_in + ((size_t)(b << 10) + d) * 32);
    float so[32];
#pragma unroll
    for (int q = 1; q < 8; q++) {
        float4 t4 = ((const float4*)stp)[q];
        so[q * 4 - 4] = t4.x; so[q * 4 - 3] = t4.y; so[q * 4 - 2] = t4.z; so[q * 4 - 1] = t4.w;
    }
#pragma unroll
    for (int j = 0; j < 4; j++) so[28 + j] = hsm[j][lane][w];
    float* o1 = out + ((size_t)(b << 10) + d) * 32;
#pragma unroll
    for (int q = 0; q < 8; q++) {
        float4 v1 = { so[q * 4], so[q * 4 + 1], so[q * 4 + 2], so[q * 4 + 3] };
        ((float4*)o1)[q] = v1;
    }
}

// ================= final assembly: at half + synchrony =================
__global__ void __launch_bounds__(256) k_fin_at(
    float* __restrict__ out,
    const float* __restrict__ at_in, const float* __restrict__ start_at) {
    int tid = threadIdx.x;
    if (blockIdx.x < 1024) {
        int local = blockIdx.x;
        int dt = local & 127, bt = local >> 7;
        int d0 = dt * 8, b0 = bt * 32;
        int w = tid >> 5, lane = tid & 31;
        int d = d0 + w, b = b0 + lane;
        bool done = g_dones[b] != 0;
        const float* atp = done ? (start_at + d * 32) : (at_in + ((size_t)(b << 10) + d) * 32);
        float ao[32];
#pragma unroll
        for (int q = 1; q < 8; q++) {
            float4 u4 = ((const float4*)atp)[q];
            ao[q * 4 - 4] = u4.x; ao[q * 4 - 3] = u4.y; ao[q * 4 - 2] = u4.z; ao[q * 4 - 1] = u4.w;
        }
#pragma unroll
        for (int j = 0; j < 4; j++) ao[28 + j] = g_hat[j][(size_t)d * Bx + b];
        float* o2 = out + BDMx + ((size_t)(b << 10) + d) * 32;
#pragma unroll
        for (int q = 0; q < 8; q++) {
            float4 v2 = { ao[q * 4], ao[q * 4 + 1], ao[q * 4 + 2], ao[q * 4 + 3] };
            ((float4*)o2)[q] = v2;
        }
    } else {
        __shared__ float S[Mx * NSYx];
        int b = blockIdx.x - 1024;
        bool done = g_dones[b] != 0;
        float* outs = out + 2 * (size_t)BDMx;
        for (int t = tid; t < Mx * NSYx; t += 256) {
            int m = t & 31, j = t >> 5;
            int dd = Dx - NSYx + j;
            float val;
            if (m < 28)
                val = done ? start_at[dd * 32 + m + 4]
                           : at_in[((size_t)(b * Dx + dd)) * 32 + m + 4];
            else
                val = g_hat[m - 28][(size_t)dd * Bx + b];
            S[m * NSYx + j] = val;
        }
        __syncthreads();
        for (int s = tid; s < SYNCHx; s += 256) {
            int ti = g_tri_i[s], tj = g_tri_j[s];
            float acc = 0.0f;
#pragma unroll
            for (int m = 0; m < Mx; m++)
                acc += g_decay[m * SYNCHx + s] * S[m * NSYx + ti] * S[m * NSYx + tj];
            outs[(size_t)b * SYNCHx + s] = acc * g_invden[s];
        }
    }
}

// =====================================================================
extern "C" void kernel_launch(void* const* d_in, const int* in_sizes, int n_in,
                              void* d_out, int out_size) {
    (void)in_sizes; (void)n_in; (void)out_size;
    const float* obs      = (const float*)d_in[0];
    const unsigned char* dones_raw = (const unsigned char*)d_in[1];
    const float* st_in    = (const float*)d_in[3];
    const float* at_in    = (const float*)d_in[4];
    const float* start_st = (const float*)d_in[5];
    const float* start_at = (const float*)d_in[6];
    const float* bb_w1    = (const float*)d_in[7];
    const float* bb_b1    = (const float*)d_in[8];
    const float* ln1s     = (const float*)d_in[9];
    const float* ln1b     = (const float*)d_in[10];
    const float* bb_w2    = (const float*)d_in[11];
    const float* bb_b2    = (const float*)d_in[12];
    const float* ln2s     = (const float*)d_in[13];
    const float* ln2b     = (const float*)d_in[14];
    const float* syn_w1   = (const float*)d_in[15];
    const float* syn_b1   = (const float*)d_in[16];
    const float* sln1s    = (const float*)d_in[17];
    const float* sln1b    = (const float*)d_in[18];
    const float* syn_w2   = (const float*)d_in[19];
    const float* syn_b2   = (const float*)d_in[20];
    const float* sln2s    = (const float*)d_in[21];
    const float* sln2b    = (const float*)d_in[22];
    const float* nlm1_w   = (const float*)d_in[23];
    const float* nlm1_b   = (const float*)d_in[24];
    const float* nlm1_T   = (const float*)d_in[25];
    const float* nlm2_w   = (const float*)d_in[26];
    const float* nlm2_b   = (const float*)d_in[27];
    const float* nlm2_T   = (const float*)d_in[28];
    const float* decay_p  = (const float*)d_in[29];
    float* out = (float*)d_out;

    void *p_y, *p_hst;
    void *p_obshi, *p_obslo, *p_prehi, *p_prelo, *p_h1hi, *p_h1lo;
    void *p_wb1h, *p_wb1l, *p_wb2h, *p_wb2l, *p_ws1h, *p_ws1l, *p_ws2h, *p_ws2l;
    cudaGetSymbolAddress(&p_y, g_y);
    cudaGetSymbolAddress(&p_hst, g_hst);
    cudaGetSymbolAddress(&p_obshi, g_obshi);  cudaGetSymbolAddress(&p_obslo, g_obslo);
    cudaGetSymbolAddress(&p_prehi, g_prehi);  cudaGetSymbolAddress(&p_prelo, g_prelo);
    cudaGetSymbolAddress(&p_h1hi, g_h1hi);    cudaGetSymbolAddress(&p_h1lo, g_h1lo);
    cudaGetSymbolAddress(&p_wb1h, g_wb1hi);   cudaGetSymbolAddress(&p_wb1l, g_wb1lo);
    cudaGetSymbolAddress(&p_wb2h, g_wb2hi);   cudaGetSymbolAddress(&p_wb2l, g_wb2lo);
    cudaGetSymbolAddress(&p_ws1h, g_ws1hi);   cudaGetSymbolAddress(&p_ws1l, g_ws1lo);
    cudaGetSymbolAddress(&p_ws2h, g_ws2hi);   cudaGetSymbolAddress(&p_ws2l, g_ws2lo);
    float* gy   = (float*)p_y;
    float* ghst = (float*)p_hst;

    static int init_done = 0;
    static cudaStream_t s_side = nullptr;
    static cudaEvent_t ev_fork = nullptr, ev_join = nullptr;
    static cudaEvent_t ev_fork2 = nullptr, ev_join2 = nullptr;
    int gsmem = GSTAGES * GBUF_BYTES + 1024;
    if (!init_done) {
        cudaFuncSetAttribute(k_tgemm, cudaFuncAttributeMaxDynamicSharedMemorySize, gsmem);
        cudaStreamCreateWithFlags(&s_side, cudaStreamNonBlocking);
        cudaEventCreateWithFlags(&ev_fork, cudaEventDisableTiming);
        cudaEventCreateWithFlags(&ev_join, cudaEventDisableTiming);
        cudaEventCreateWithFlags(&ev_fork2, cudaEventDisableTiming);
        cudaEventCreateWithFlags(&ev_join2, cudaEventDisableTiming);
        init_done = 1;
    }

    // fork: side branch preps NLM + synapse weights
    cudaEventRecord(ev_fork, 0);
    cudaStreamWaitEvent(s_side, ev_fork, 0);
    k_prep_side<<<9216, 256, 0, s_side>>>(nlm1_w, nlm2_w, syn_w1, syn_w2);
    cudaEventRecord(ev_join, s_side);

    // main branch: light prep + backbone
    k_prep_main<<<1034, 256>>>(dones_raw, decay_p, obs, bb_w1, bb_w2);

    k_tgemm<<<dim3(16, 4, 2), 256, gsmem>>>(
        (const __nv_bfloat16*)p_obshi, (const __nv_bfloat16*)p_obslo,
        (const __nv_bfloat16*)p_wb1h, (const __nv_bfloat16*)p_wb1l,
        gy, 0, 128, 256, 256, 1024);
    k_gluln_split<2><<<Bx, 512>>>(gy, 512, bb_b1, ln1s, ln1b,
        (__nv_bfloat16*)p_h1hi, (__nv_bfloat16*)p_h1lo, 512, 0, nullptr, nullptr);
    k_tgemm<<<dim3(16, 4, 2), 256, gsmem>>>(
        (const __nv_bfloat16*)p_h1hi, (const __nv_bfloat16*)p_h1lo,
        (const __nv_bfloat16*)p_wb2h, (const __nv_bfloat16*)p_wb2l,
        gy, 0, 256, 512, 512, 1024);
    k_gluln_split<2><<<Bx, 512>>>(gy, 512, bb_b2, ln2s, ln2b,
        (__nv_bfloat16*)p_prehi, (__nv_bfloat16*)p_prelo, 1536, 1, at_in, start_at);

    // join: synapse + NLM weights ready
    cudaStreamWaitEvent(0, ev_join, 0);

    // hoisted f-part of synapse GEMM1 (iteration-invariant): K=0..512 -> slice 2
    k_tgemm<<<dim3(32, 4, 1), 256, gsmem>>>(
        (const __nv_bfloat16*)p_prehi, (const __nv_bfloat16*)p_prelo,
        (const __nv_bfloat16*)p_ws1h, (const __nv_bfloat16*)p_ws1l,
        gy + 2 * (size_t)Bx * 2048, 0, 512, 1536, 1536, 2048);

    for (int i = 0; i < ITERSx; i++) {
        // synapse GEMM1, at-part only: K=512..1536, KS=2
        k_tgemm<<<dim3(32, 4, 2), 256, gsmem>>>(
            (const __nv_bfloat16*)p_prehi, (const __nv_bfloat16*)p_prelo,
            (const __nv_bfloat16*)p_ws1h, (const __nv_bfloat16*)p_ws1l,
            gy, 512, 512, 1536, 1536, 2048);
        k_gluln_split<3><<<Bx, 1024>>>(gy, 1024, syn_b1, sln1s, sln1b,
            (__nv_bfloat16*)p_h1hi, (__nv_bfloat16*)p_h1lo, 1024, 0, nullptr, nullptr);
        // synapse GEMM2 K=1024, KS=2
        k_tgemm<<<dim3(32, 4, 2), 256, gsmem>>>(
            (const __nv_bfloat16*)p_h1hi, (const __nv_bfloat16*)p_h1lo,
            (const __nv_bfloat16*)p_ws2h, (const __nv_bfloat16*)p_ws2l,
            gy, 0, 512, 1024, 1024, 2048);
        k_gluln_f32<2><<<Bx, 1024>>>(gy, 1024, syn_b2, sln2s, sln2b,
            ghst + (size_t)i * BDx);
        if (i == ITERSx - 1) {
            // st-half of finalization depends only on g_hst: overlap with nlm<3>
            cudaEventRecord(ev_fork2, 0);
            cudaStreamWaitEvent(s_side, ev_fork2, 0);
            k_fin_st<<<1024, 256, 0, s_side>>>(out, st_in, start_st);
            cudaEventRecord(ev_join2, s_side);
        }
        switch (i) {
            case 0: k_nlm_tc<0><<<1024, 256>>>(st_in, start_st, nlm1_b, nlm1_T, nlm2_b, nlm2_T); break;
            case 1: k_nlm_tc<1><<<1024, 256>>>(st_in, start_st, nlm1_b, nlm1_T, nlm2_b, nlm2_T); break;
            case 2: k_nlm_tc<2><<<1024, 256>>>(st_in, start_st, nlm1_b, nlm1_T, nlm2_b, nlm2_T); break;
            case 3: k_nlm_tc<3><<<1024, 256>>>(st_in, start_st, nlm1_b, nlm1_T, nlm2_b, nlm2_T); break;
        }
    }

    k_fin_at<<<1024 + Bx, 256>>>(out, at_in, start_at);
    cudaStreamWaitEvent(0, ev_join2, 0);
}